// round 2
// baseline (speedup 1.0000x reference)
#include <cuda_runtime.h>
#include <math.h>

// Problem constants (GAT_19301583028500)
#define NN   50000      // nodes
#define EE   800000     // edges
#define IN_F 256        // in features (== H*F)
#define HH   4          // heads
#define FF   64         // per-head out features
#define SLOPE 0.2f

// ---------------- device scratch (no allocations allowed) ----------------
__device__ float4 g_proj [NN * (IN_F/4)];   // [N,256] projected features (51.2 MB)
__device__ float4 g_e    [EE];              // [E,4] edge scores -> exp(scores) (12.8 MB)
__device__ float4 g_ssrc [NN];              // [N,4] source scores
__device__ float4 g_strg [NN];              // [N,4] target scores
__device__ float4 g_denom[NN];              // [N,4] softmax denominators
__device__ int    g_maxbits;                // ordered-int encoding of global max

__device__ __forceinline__ float leaky(float v) { return v > 0.f ? v : SLOPE * v; }

// monotone float<->int encoding for atomicMax over signed floats (involution)
__device__ __forceinline__ int   ford(float f) { int i = __float_as_int(f); return i >= 0 ? i : i ^ 0x7fffffff; }
__device__ __forceinline__ float finv(int i)   { return __int_as_float(i >= 0 ? i : i ^ 0x7fffffff); }

__device__ __forceinline__ void red_add_v4(float* p, float x, float y, float z, float w) {
    asm volatile("red.global.add.v4.f32 [%0], {%1, %2, %3, %4};"
                 :: "l"(p), "f"(x), "f"(y), "f"(z), "f"(w) : "memory");
}

// ---------------- init: zero denom, reset global max ----------------
__global__ void init_kernel() {
    int i = blockIdx.x * blockDim.x + threadIdx.x;
    if (i < NN) g_denom[i] = make_float4(0.f, 0.f, 0.f, 0.f);
    if (i == 0) g_maxbits = ford(-INFINITY);
}

// ---------------- tiled SGEMM: C[M,256] = A[M,256] @ B[256,256] (+bias) ----------------
// BM=128, BN=64, BK=16; 256 threads; 8x4 microtile per thread.
__global__ __launch_bounds__(256) void sgemm256(const float* __restrict__ A,
                                                const float* __restrict__ B,
                                                float* __restrict__ C,
                                                const float* __restrict__ bias,
                                                int M) {
    const int K = 256, NC = 256;
    __shared__ float As[16][128];   // transposed A tile: As[k][row]
    __shared__ float Bs[16][64];

    int tid = threadIdx.x;
    int tx = tid & 15;          // col group (4 cols)
    int ty = tid >> 4;          // row group (8 rows)
    int rowBase = blockIdx.x * 128;
    int colBase = blockIdx.y * 64;

    float acc[8][4];
    #pragma unroll
    for (int i = 0; i < 8; i++)
        #pragma unroll
        for (int j = 0; j < 4; j++) acc[i][j] = 0.f;

    for (int k0 = 0; k0 < K; k0 += 16) {
        // A tile: 128x16 = 512 float4, 2 per thread
        #pragma unroll
        for (int it = 0; it < 2; it++) {
            int q = tid + it * 256;
            int r = q >> 2;
            int kc = (q & 3) << 2;
            float4 v = make_float4(0.f, 0.f, 0.f, 0.f);
            int grow = rowBase + r;
            if (grow < M) v = *(const float4*)&A[grow * K + k0 + kc];
            As[kc + 0][r] = v.x; As[kc + 1][r] = v.y;
            As[kc + 2][r] = v.z; As[kc + 3][r] = v.w;
        }
        // B tile: 16x64 = 256 float4, 1 per thread
        {
            int kr = tid >> 4;
            int cc = (tid & 15) << 2;
            float4 v = *(const float4*)&B[(k0 + kr) * NC + colBase + cc];
            *(float4*)&Bs[kr][cc] = v;
        }
        __syncthreads();

        #pragma unroll
        for (int k = 0; k < 16; k++) {
            float4 a0 = *(float4*)&As[k][ty * 8];
            float4 a1 = *(float4*)&As[k][ty * 8 + 4];
            float4 b  = *(float4*)&Bs[k][tx * 4];
            float ar[8] = {a0.x, a0.y, a0.z, a0.w, a1.x, a1.y, a1.z, a1.w};
            float br[4] = {b.x, b.y, b.z, b.w};
            #pragma unroll
            for (int i = 0; i < 8; i++)
                #pragma unroll
                for (int j = 0; j < 4; j++)
                    acc[i][j] += ar[i] * br[j];
        }
        __syncthreads();
    }

    float bv[4] = {0.f, 0.f, 0.f, 0.f};
    if (bias) {
        float4 b = *(const float4*)&bias[colBase + tx * 4];
        bv[0] = b.x; bv[1] = b.y; bv[2] = b.z; bv[3] = b.w;
    }
    #pragma unroll
    for (int i = 0; i < 8; i++) {
        int grow = rowBase + ty * 8 + i;
        if (grow < M) {
            float4 o;
            o.x = acc[i][0] + bv[0];
            o.y = acc[i][1] + bv[1];
            o.z = acc[i][2] + bv[2];
            o.w = acc[i][3] + bv[3];
            *(float4*)&C[grow * NC + colBase + tx * 4] = o;
        }
    }
}

// ---------------- per-node attention scores: warp per (n,h) ----------------
__global__ void scores_kernel(const float* __restrict__ a_src,
                              const float* __restrict__ a_trg) {
    int w = (blockIdx.x * blockDim.x + threadIdx.x) >> 5;
    int lane = threadIdx.x & 31;
    if (w >= NN * HH) return;
    int n = w >> 2, h = w & 3;
    const float* p = (const float*)g_proj + n * 256 + h * 64;
    float p0 = p[lane], p1 = p[lane + 32];
    float vs = p0 * a_src[h * 64 + lane] + p1 * a_src[h * 64 + lane + 32];
    float vt = p0 * a_trg[h * 64 + lane] + p1 * a_trg[h * 64 + lane + 32];
    #pragma unroll
    for (int o = 16; o; o >>= 1) {
        vs += __shfl_xor_sync(0xffffffffu, vs, o);
        vt += __shfl_xor_sync(0xffffffffu, vt, o);
    }
    if (lane == 0) {
        ((float*)g_ssrc)[w] = vs;
        ((float*)g_strg)[w] = vt;
    }
}

// ---------------- edge pass A: e = leaky(s_src[src]+s_trg[trg]); track global max ----------------
__global__ void edgeA_kernel(const int* __restrict__ esrc, const int* __restrict__ etrg) {
    int e = blockIdx.x * blockDim.x + threadIdx.x;
    float lmax = -INFINITY;
    if (e < EE) {
        int s = esrc[e], t = etrg[e];
        float4 ss = g_ssrc[s];
        float4 st = g_strg[t];
        float4 v;
        v.x = leaky(ss.x + st.x);
        v.y = leaky(ss.y + st.y);
        v.z = leaky(ss.z + st.z);
        v.w = leaky(ss.w + st.w);
        g_e[e] = v;
        lmax = fmaxf(fmaxf(v.x, v.y), fmaxf(v.z, v.w));
    }
    #pragma unroll
    for (int o = 16; o; o >>= 1)
        lmax = fmaxf(lmax, __shfl_xor_sync(0xffffffffu, lmax, o));
    if ((threadIdx.x & 31) == 0)
        atomicMax(&g_maxbits, ford(lmax));
}

// ---------------- edge pass B: ex = exp(e - max); denom[trg] += ex ----------------
__global__ void edgeB_kernel(const int* __restrict__ etrg) {
    int e = blockIdx.x * blockDim.x + threadIdx.x;
    if (e >= EE) return;
    float m = finv(g_maxbits);
    int t = etrg[e];
    float4 v = g_e[e];
    v.x = expf(v.x - m);
    v.y = expf(v.y - m);
    v.z = expf(v.z - m);
    v.w = expf(v.w - m);
    g_e[e] = v;
    red_add_v4((float*)&g_denom[t], v.x, v.y, v.z, v.w);
}

// ---------------- edge pass C: warp per edge, out[trg] += proj[src] * attn ----------------
__global__ __launch_bounds__(256) void edgeC_kernel(const int* __restrict__ esrc,
                                                    const int* __restrict__ etrg,
                                                    float* __restrict__ out) {
    int w = (blockIdx.x * blockDim.x + threadIdx.x) >> 5;
    if (w >= EE) return;
    int lane = threadIdx.x & 31;
    int s = esrc[w], t = etrg[w];

    float4 ex = g_e[w];
    float4 d  = g_denom[t];
    float attn[4];
    attn[0] = ex.x / (d.x + 1e-16f);
    attn[1] = ex.y / (d.y + 1e-16f);
    attn[2] = ex.z / (d.z + 1e-16f);
    attn[3] = ex.w / (d.w + 1e-16f);

    const float4* prow = &g_proj[s * 64];
    float4 p0 = prow[lane];
    float4 p1 = prow[lane + 32];
    float a0 = attn[lane >> 4];
    float a1 = attn[2 + (lane >> 4)];

    float* orow = out + t * 256;
    red_add_v4(orow + lane * 4,        p0.x * a0, p0.y * a0, p0.z * a0, p0.w * a0);
    red_add_v4(orow + 128 + lane * 4,  p1.x * a1, p1.y * a1, p1.z * a1, p1.w * a1);
}

// ---------------- final: out = leaky(out) in place ----------------
__global__ void final_kernel(float* __restrict__ out) {
    int i = blockIdx.x * blockDim.x + threadIdx.x;
    if (i >= NN * 64) return;  // float4 count
    float4 v = ((float4*)out)[i];
    v.x = leaky(v.x); v.y = leaky(v.y); v.z = leaky(v.z); v.w = leaky(v.w);
    ((float4*)out)[i] = v;
}

// ---------------- launch ----------------
extern "C" void kernel_launch(void* const* d_in, const int* in_sizes, int n_in,
                              void* d_out, int out_size) {
    const float* x      = (const float*)d_in[0];
    const float* W      = (const float*)d_in[1];
    const float* a_src  = (const float*)d_in[2];
    const float* a_trg  = (const float*)d_in[3];
    const float* skip_w = (const float*)d_in[4];
    const float* bias   = (const float*)d_in[5];
    const int*   esrc   = (const int*)d_in[6];
    const int*   etrg   = (const int*)d_in[7];
    float* out = (float*)d_out;

    float* proj;
    cudaGetSymbolAddress((void**)&proj, g_proj);

    // 1. init scratch
    init_kernel<<<(NN + 255) / 256, 256>>>();

    // 2. proj = x @ W   (into scratch)
    dim3 ggrid((NN + 127) / 128, 256 / 64);
    sgemm256<<<ggrid, 256>>>(x, W, proj, nullptr, NN);

    // 3. pre_out = x @ skip_w + bias   (into d_out)
    sgemm256<<<ggrid, 256>>>(x, skip_w, out, bias, NN);

    // 4. per-node attention scores
    scores_kernel<<<(NN * HH * 32 + 255) / 256, 256>>>(a_src, a_trg);

    // 5. edge scoring + global max
    edgeA_kernel<<<(EE + 255) / 256, 256>>>(esrc, etrg);

    // 6. exp + denom
    edgeB_kernel<<<(EE + 255) / 256, 256>>>(etrg);

    // 7. scatter aggregation (warp per edge)
    edgeC_kernel<<<(EE * 32 + 255) / 256, 256>>>(esrc, etrg, out);

    // 8. output activation
    final_kernel<<<(NN * 64 + 255) / 256, 256>>>(out);
}

// round 3
// speedup vs baseline: 1.6528x; 1.6528x over previous
#include <cuda_runtime.h>
#include <math.h>

// Problem constants (GAT_19301583028500)
#define NN   50000      // nodes
#define EE   800000     // edges
#define IN_F 256        // in features (== H*F)
#define HH   4          // heads
#define FF   64         // per-head out features
#define SLOPE 0.2f

// ---------------- device scratch (no allocations allowed) ----------------
__device__ float4 g_proj [NN * (IN_F/4)];   // [N,256] projected features (51.2 MB)
__device__ float4 g_e    [EE];              // [E,4] edge scores -> exp(scores) (12.8 MB)
__device__ float4 g_ssrc [NN];              // [N,4] source scores
__device__ float4 g_strg [NN];              // [N,4] target scores
__device__ float4 g_denom[NN];              // [N,4] softmax denominators
__device__ int    g_maxbits;                // ordered-int encoding of global max

__device__ __forceinline__ float leaky(float v) { return v > 0.f ? v : SLOPE * v; }

__device__ __forceinline__ int   ford(float f) { int i = __float_as_int(f); return i >= 0 ? i : i ^ 0x7fffffff; }
__device__ __forceinline__ float finv(int i)   { return __int_as_float(i >= 0 ? i : i ^ 0x7fffffff); }

__device__ __forceinline__ void red_add_v4(float* p, float x, float y, float z, float w) {
    asm volatile("red.global.add.v4.f32 [%0], {%1, %2, %3, %4};"
                 :: "l"(p), "f"(x), "f"(y), "f"(z), "f"(w) : "memory");
}

__device__ __forceinline__ unsigned cvt_tf32(float f) {
    unsigned r;
    asm("cvt.rna.tf32.f32 %0, %1;" : "=r"(r) : "f"(f));
    return r;
}

__device__ __forceinline__ void cp_async16(unsigned smem_addr, const void* gptr) {
    asm volatile("cp.async.cg.shared.global [%0], [%1], 16;"
                 :: "r"(smem_addr), "l"(gptr) : "memory");
}
__device__ __forceinline__ void cp_commit() { asm volatile("cp.async.commit_group;" ::: "memory"); }
template<int N_> __device__ __forceinline__ void cp_wait() {
    asm volatile("cp.async.wait_group %0;" :: "n"(N_) : "memory");
}

// ---------------- init ----------------
__global__ void init_kernel() {
    int i = blockIdx.x * blockDim.x + threadIdx.x;
    if (i < NN) g_denom[i] = make_float4(0.f, 0.f, 0.f, 0.f);
    if (i == 0) g_maxbits = ford(-INFINITY);
}

// ---------------- tf32 tensor-core GEMM ----------------
// C[M,256] = A[M,256] @ B[256,256] (+ optional bias)
// CTA tile 128x128, BK=16, 8 warps (warp tile 64x32), mma.m16n8k8.tf32.
// Double-buffered cp.async pipeline. Conflict-free smem via stride padding:
//   As[row][k]: stride 20 floats  -> frag addr (20*gid + c) mod 32 distinct
//   Bs[k][n]  : stride 136 floats -> frag addr (8*k + n)   mod 32 distinct
#define GA_STRIDE 20
#define GB_STRIDE 136

__global__ __launch_bounds__(256) void gemm_tf32(const float* __restrict__ A,
                                                 const float* __restrict__ B0,
                                                 const float* __restrict__ B1,
                                                 float* __restrict__ C0,
                                                 float* __restrict__ C1,
                                                 const float* __restrict__ bias,
                                                 int M) {
    __shared__ float As[2][128 * GA_STRIDE];   // 10240 B per stage
    __shared__ float Bs[2][16  * GB_STRIDE];   //  8704 B per stage

    const float* B = (blockIdx.z == 0) ? B0 : B1;
    float*       C = (blockIdx.z == 0) ? C0 : C1;
    const bool use_bias = (blockIdx.z == 1);

    const int K = 256, NC = 256;
    const int tid  = threadIdx.x;
    const int wid  = tid >> 5;
    const int lane = tid & 31;
    const int gid  = lane >> 2;     // group id (0..7)
    const int tig  = lane & 3;      // thread in group (0..3)
    const int warp_m = wid & 1;     // 0..1  (64-row slabs)
    const int warp_n = wid >> 1;    // 0..3  (32-col slabs)

    const int rowBase = blockIdx.x * 128;
    const int colBase = blockIdx.y * 128;

    float acc[4][4][4];
    #pragma unroll
    for (int i = 0; i < 4; i++)
        #pragma unroll
        for (int j = 0; j < 4; j++)
            #pragma unroll
            for (int q = 0; q < 4; q++) acc[i][j][q] = 0.f;

    // per-thread cp.async assignments
    // A tile: 128 rows x 16 floats = 512 float4 -> 2 per thread
    int aq0 = tid, aq1 = tid + 256;
    int ar0 = aq0 >> 2, as0 = aq0 & 3;
    int ar1 = aq1 >> 2, as1 = aq1 & 3;
    int grow0 = min(rowBase + ar0, M - 1);
    int grow1 = min(rowBase + ar1, M - 1);
    // B tile: 16 rows x 32 float4 = 512 -> 2 per thread
    int bq0 = tid, bq1 = tid + 256;
    int br0 = bq0 >> 5, bs0 = bq0 & 31;
    int br1 = bq1 >> 5, bs1 = bq1 & 31;

    unsigned sA[2], sB[2];
    sA[0] = (unsigned)__cvta_generic_to_shared(&As[0][0]);
    sA[1] = (unsigned)__cvta_generic_to_shared(&As[1][0]);
    sB[0] = (unsigned)__cvta_generic_to_shared(&Bs[0][0]);
    sB[1] = (unsigned)__cvta_generic_to_shared(&Bs[1][0]);

    auto prefetch = [&](int kt, int buf) {
        const float* ga0 = &A[(long)grow0 * K + kt * 16 + as0 * 4];
        const float* ga1 = &A[(long)grow1 * K + kt * 16 + as1 * 4];
        cp_async16(sA[buf] + (ar0 * GA_STRIDE + as0 * 4) * 4, ga0);
        cp_async16(sA[buf] + (ar1 * GA_STRIDE + as1 * 4) * 4, ga1);
        const float* gb0 = &B[(kt * 16 + br0) * NC + colBase + bs0 * 4];
        const float* gb1 = &B[(kt * 16 + br1) * NC + colBase + bs1 * 4];
        cp_async16(sB[buf] + (br0 * GB_STRIDE + bs0 * 4) * 4, gb0);
        cp_async16(sB[buf] + (br1 * GB_STRIDE + bs1 * 4) * 4, gb1);
    };

    prefetch(0, 0);
    cp_commit();

    const int KT = K / 16;   // 16 k-tiles
    for (int kt = 0; kt < KT; kt++) {
        int buf = kt & 1;
        if (kt + 1 < KT) {
            prefetch(kt + 1, buf ^ 1);
            cp_commit();
            cp_wait<1>();
        } else {
            cp_wait<0>();
        }
        __syncthreads();

        #pragma unroll
        for (int ks = 0; ks < 2; ks++) {
            unsigned af[4][4];
            #pragma unroll
            for (int mt = 0; mt < 4; mt++) {
                int rb = warp_m * 64 + mt * 16 + gid;
                int c  = ks * 8 + tig;
                af[mt][0] = cvt_tf32(As[buf][rb * GA_STRIDE + c]);
                af[mt][1] = cvt_tf32(As[buf][(rb + 8) * GA_STRIDE + c]);
                af[mt][2] = cvt_tf32(As[buf][rb * GA_STRIDE + c + 4]);
                af[mt][3] = cvt_tf32(As[buf][(rb + 8) * GA_STRIDE + c + 4]);
            }
            unsigned bf[4][2];
            #pragma unroll
            for (int nt = 0; nt < 4; nt++) {
                int cb = warp_n * 32 + nt * 8 + gid;
                bf[nt][0] = cvt_tf32(Bs[buf][(ks * 8 + tig) * GB_STRIDE + cb]);
                bf[nt][1] = cvt_tf32(Bs[buf][(ks * 8 + tig + 4) * GB_STRIDE + cb]);
            }
            #pragma unroll
            for (int mt = 0; mt < 4; mt++)
                #pragma unroll
                for (int nt = 0; nt < 4; nt++) {
                    asm volatile(
                        "mma.sync.aligned.m16n8k8.row.col.f32.tf32.tf32.f32 "
                        "{%0,%1,%2,%3}, {%4,%5,%6,%7}, {%8,%9}, {%0,%1,%2,%3};"
                        : "+f"(acc[mt][nt][0]), "+f"(acc[mt][nt][1]),
                          "+f"(acc[mt][nt][2]), "+f"(acc[mt][nt][3])
                        : "r"(af[mt][0]), "r"(af[mt][1]), "r"(af[mt][2]), "r"(af[mt][3]),
                          "r"(bf[nt][0]), "r"(bf[nt][1]));
                }
        }
        __syncthreads();
    }

    // epilogue
    #pragma unroll
    for (int mt = 0; mt < 4; mt++) {
        int r0 = rowBase + warp_m * 64 + mt * 16 + gid;
        int r1 = r0 + 8;
        #pragma unroll
        for (int nt = 0; nt < 4; nt++) {
            int col = colBase + warp_n * 32 + nt * 8 + 2 * tig;
            float b0 = 0.f, b1 = 0.f;
            if (use_bias) { b0 = bias[col]; b1 = bias[col + 1]; }
            if (r0 < M) {
                float2 v = make_float2(acc[mt][nt][0] + b0, acc[mt][nt][1] + b1);
                *(float2*)&C[(long)r0 * NC + col] = v;
            }
            if (r1 < M) {
                float2 v = make_float2(acc[mt][nt][2] + b0, acc[mt][nt][3] + b1);
                *(float2*)&C[(long)r1 * NC + col] = v;
            }
        }
    }
}

// ---------------- per-node attention scores: warp per (n,h) ----------------
__global__ void scores_kernel(const float* __restrict__ a_src,
                              const float* __restrict__ a_trg) {
    int w = (blockIdx.x * blockDim.x + threadIdx.x) >> 5;
    int lane = threadIdx.x & 31;
    if (w >= NN * HH) return;
    int n = w >> 2, h = w & 3;
    const float* p = (const float*)g_proj + n * 256 + h * 64;
    float p0 = p[lane], p1 = p[lane + 32];
    float vs = p0 * a_src[h * 64 + lane] + p1 * a_src[h * 64 + lane + 32];
    float vt = p0 * a_trg[h * 64 + lane] + p1 * a_trg[h * 64 + lane + 32];
    #pragma unroll
    for (int o = 16; o; o >>= 1) {
        vs += __shfl_xor_sync(0xffffffffu, vs, o);
        vt += __shfl_xor_sync(0xffffffffu, vt, o);
    }
    if (lane == 0) {
        ((float*)g_ssrc)[w] = vs;
        ((float*)g_strg)[w] = vt;
    }
}

// ---------------- edge pass A: e = leaky(s_src[src]+s_trg[trg]); global max ----------------
__global__ void edgeA_kernel(const int* __restrict__ esrc, const int* __restrict__ etrg) {
    int e = blockIdx.x * blockDim.x + threadIdx.x;
    float lmax = -INFINITY;
    if (e < EE) {
        int s = esrc[e], t = etrg[e];
        float4 ss = g_ssrc[s];
        float4 st = g_strg[t];
        float4 v;
        v.x = leaky(ss.x + st.x);
        v.y = leaky(ss.y + st.y);
        v.z = leaky(ss.z + st.z);
        v.w = leaky(ss.w + st.w);
        g_e[e] = v;
        lmax = fmaxf(fmaxf(v.x, v.y), fmaxf(v.z, v.w));
    }
    #pragma unroll
    for (int o = 16; o; o >>= 1)
        lmax = fmaxf(lmax, __shfl_xor_sync(0xffffffffu, lmax, o));
    if ((threadIdx.x & 31) == 0)
        atomicMax(&g_maxbits, ford(lmax));
}

// ---------------- edge pass B: ex = exp(e - max); denom[trg] += ex ----------------
__global__ void edgeB_kernel(const int* __restrict__ etrg) {
    int e = blockIdx.x * blockDim.x + threadIdx.x;
    if (e >= EE) return;
    float m = finv(g_maxbits);
    int t = etrg[e];
    float4 v = g_e[e];
    v.x = expf(v.x - m);
    v.y = expf(v.y - m);
    v.z = expf(v.z - m);
    v.w = expf(v.w - m);
    g_e[e] = v;
    red_add_v4((float*)&g_denom[t], v.x, v.y, v.z, v.w);
}

// ---------------- edge pass C: warp per edge, out[trg] += proj[src] * attn ----------------
__global__ __launch_bounds__(256) void edgeC_kernel(const int* __restrict__ esrc,
                                                    const int* __restrict__ etrg,
                                                    float* __restrict__ out) {
    int w = (blockIdx.x * blockDim.x + threadIdx.x) >> 5;
    if (w >= EE) return;
    int lane = threadIdx.x & 31;
    int s = esrc[w], t = etrg[w];

    float4 ex = g_e[w];
    float4 d  = g_denom[t];
    float attn[4];
    attn[0] = ex.x / (d.x + 1e-16f);
    attn[1] = ex.y / (d.y + 1e-16f);
    attn[2] = ex.z / (d.z + 1e-16f);
    attn[3] = ex.w / (d.w + 1e-16f);

    const float4* prow = &g_proj[s * 64];
    float4 p0 = prow[lane];
    float4 p1 = prow[lane + 32];
    float a0 = attn[lane >> 4];
    float a1 = attn[2 + (lane >> 4)];

    float* orow = out + t * 256;
    red_add_v4(orow + lane * 4,        p0.x * a0, p0.y * a0, p0.z * a0, p0.w * a0);
    red_add_v4(orow + 128 + lane * 4,  p1.x * a1, p1.y * a1, p1.z * a1, p1.w * a1);
}

// ---------------- final: out = leaky(out) in place ----------------
__global__ void final_kernel(float* __restrict__ out) {
    int i = blockIdx.x * blockDim.x + threadIdx.x;
    if (i >= NN * 64) return;  // float4 count
    float4 v = ((float4*)out)[i];
    v.x = leaky(v.x); v.y = leaky(v.y); v.z = leaky(v.z); v.w = leaky(v.w);
    ((float4*)out)[i] = v;
}

// ---------------- launch ----------------
extern "C" void kernel_launch(void* const* d_in, const int* in_sizes, int n_in,
                              void* d_out, int out_size) {
    const float* x      = (const float*)d_in[0];
    const float* W      = (const float*)d_in[1];
    const float* a_src  = (const float*)d_in[2];
    const float* a_trg  = (const float*)d_in[3];
    const float* skip_w = (const float*)d_in[4];
    const float* bias   = (const float*)d_in[5];
    const int*   esrc   = (const int*)d_in[6];
    const int*   etrg   = (const int*)d_in[7];
    float* out = (float*)d_out;

    float* proj;
    cudaGetSymbolAddress((void**)&proj, g_proj);

    // 1. init scratch
    init_kernel<<<(NN + 255) / 256, 256>>>();

    // 2+3. both GEMMs fused in one launch: z=0 -> proj = x@W, z=1 -> out = x@skip_w + bias
    dim3 ggrid((NN + 127) / 128, 2, 2);
    gemm_tf32<<<ggrid, 256>>>(x, W, skip_w, proj, out, bias, NN);

    // 4. per-node attention scores
    scores_kernel<<<(NN * HH * 32 + 255) / 256, 256>>>(a_src, a_trg);

    // 5. edge scoring + global max
    edgeA_kernel<<<(EE + 255) / 256, 256>>>(esrc, etrg);

    // 6. exp + denom
    edgeB_kernel<<<(EE + 255) / 256, 256>>>(etrg);

    // 7. scatter aggregation (warp per edge)
    edgeC_kernel<<<(EE * 32 + 255) / 256, 256>>>(esrc, etrg, out);

    // 8. output activation
    final_kernel<<<(NN * 64 + 255) / 256, 256>>>(out);
}

// round 5
// speedup vs baseline: 2.2430x; 1.3570x over previous
#include <cuda_runtime.h>
#include <math.h>
#include <stdint.h>

// Problem constants (GAT_19301583028500)
#define NN   50000      // nodes
#define EE   800000     // edges
#define IN_F 256        // in features (== H*F)
#define HH   4          // heads
#define FF   64         // per-head out features
#define SLOPE 0.2f
#define NB   ((NN + 255) / 256)   // scan blocks = 196

// ---------------- device scratch (no allocations allowed) ----------------
__device__ float4 g_proj [NN * (IN_F/4)];   // [N,256] projected features (51.2 MB)
__device__ float4 g_e    [EE];              // [E,4] exp(leaky(score)) (12.8 MB)
__device__ float4 g_ssrc [NN];              // [N,4] source scores
__device__ float4 g_strg [NN];              // [N,4] target scores
__device__ int    g_cnt  [NN];              // per-target degree histogram
__device__ int    g_off  [NN];              // exclusive-scan offsets
__device__ int    g_fill [NN];              // scatter fill counters (== degree after)
__device__ int    g_bsum [256];             // scan block sums
__device__ int    g_boff [256];             // scanned block sums
__device__ int    g_sorted[EE];             // edge ids sorted by target

__device__ __forceinline__ float leaky(float v) { return v > 0.f ? v : SLOPE * v; }

__device__ __forceinline__ unsigned cvt_tf32(float f) {
    unsigned r;
    asm("cvt.rna.tf32.f32 %0, %1;" : "=r"(r) : "f"(f));
    return r;
}
__device__ __forceinline__ void cp_async16(unsigned smem_addr, const void* gptr) {
    asm volatile("cp.async.cg.shared.global [%0], [%1], 16;"
                 :: "r"(smem_addr), "l"(gptr) : "memory");
}
__device__ __forceinline__ void cp_commit() { asm volatile("cp.async.commit_group;" ::: "memory"); }
template<int N_> __device__ __forceinline__ void cp_wait() {
    asm volatile("cp.async.wait_group %0;" :: "n"(N_) : "memory");
}

// ---------------- init: zero histogram + fill counters ----------------
__global__ void init_kernel() {
    int i = blockIdx.x * blockDim.x + threadIdx.x;
    if (i < NN) { g_cnt[i] = 0; g_fill[i] = 0; }
}

// ---------------- tf32 tensor-core GEMM (round-3 proven kernel) ----------------
// C[M,256] = A[M,256] @ B[256,256] (+ optional bias)
// CTA tile 128x128, BK=16, 8 warps (warp tile 64x32), mma.m16n8k8.tf32.
#define GA_STRIDE 20
#define GB_STRIDE 136

__global__ __launch_bounds__(256) void gemm_tf32(const float* __restrict__ A,
                                                 const float* __restrict__ B0,
                                                 const float* __restrict__ B1,
                                                 float* __restrict__ C0,
                                                 float* __restrict__ C1,
                                                 const float* __restrict__ bias,
                                                 int M) {
    __shared__ float As[2][128 * GA_STRIDE];
    __shared__ float Bs[2][16  * GB_STRIDE];

    const float* B = (blockIdx.z == 0) ? B0 : B1;
    float*       C = (blockIdx.z == 0) ? C0 : C1;
    const bool use_bias = (blockIdx.z == 1);

    const int K = 256, NC = 256;
    const int tid  = threadIdx.x;
    const int wid  = tid >> 5;
    const int lane = tid & 31;
    const int gid  = lane >> 2;
    const int tig  = lane & 3;
    const int warp_m = wid & 1;
    const int warp_n = wid >> 1;

    const int rowBase = blockIdx.x * 128;
    const int colBase = blockIdx.y * 128;

    float acc[4][4][4];
    #pragma unroll
    for (int i = 0; i < 4; i++)
        #pragma unroll
        for (int j = 0; j < 4; j++)
            #pragma unroll
            for (int q = 0; q < 4; q++) acc[i][j][q] = 0.f;

    int aq0 = tid, aq1 = tid + 256;
    int ar0 = aq0 >> 2, as0 = aq0 & 3;
    int ar1 = aq1 >> 2, as1 = aq1 & 3;
    int grow0 = min(rowBase + ar0, M - 1);
    int grow1 = min(rowBase + ar1, M - 1);
    int bq0 = tid, bq1 = tid + 256;
    int br0 = bq0 >> 5, bs0 = bq0 & 31;
    int br1 = bq1 >> 5, bs1 = bq1 & 31;

    unsigned sA[2], sB[2];
    sA[0] = (unsigned)__cvta_generic_to_shared(&As[0][0]);
    sA[1] = (unsigned)__cvta_generic_to_shared(&As[1][0]);
    sB[0] = (unsigned)__cvta_generic_to_shared(&Bs[0][0]);
    sB[1] = (unsigned)__cvta_generic_to_shared(&Bs[1][0]);

    auto prefetch = [&](int kt, int buf) {
        const float* ga0 = &A[(long)grow0 * K + kt * 16 + as0 * 4];
        const float* ga1 = &A[(long)grow1 * K + kt * 16 + as1 * 4];
        cp_async16(sA[buf] + (ar0 * GA_STRIDE + as0 * 4) * 4, ga0);
        cp_async16(sA[buf] + (ar1 * GA_STRIDE + as1 * 4) * 4, ga1);
        const float* gb0 = &B[(kt * 16 + br0) * NC + colBase + bs0 * 4];
        const float* gb1 = &B[(kt * 16 + br1) * NC + colBase + bs1 * 4];
        cp_async16(sB[buf] + (br0 * GB_STRIDE + bs0 * 4) * 4, gb0);
        cp_async16(sB[buf] + (br1 * GB_STRIDE + bs1 * 4) * 4, gb1);
    };

    prefetch(0, 0);
    cp_commit();

    const int KT = K / 16;
    for (int kt = 0; kt < KT; kt++) {
        int buf = kt & 1;
        if (kt + 1 < KT) {
            prefetch(kt + 1, buf ^ 1);
            cp_commit();
            cp_wait<1>();
        } else {
            cp_wait<0>();
        }
        __syncthreads();

        #pragma unroll
        for (int ks = 0; ks < 2; ks++) {
            unsigned af[4][4];
            #pragma unroll
            for (int mt = 0; mt < 4; mt++) {
                int rb = warp_m * 64 + mt * 16 + gid;
                int c  = ks * 8 + tig;
                af[mt][0] = cvt_tf32(As[buf][rb * GA_STRIDE + c]);
                af[mt][1] = cvt_tf32(As[buf][(rb + 8) * GA_STRIDE + c]);
                af[mt][2] = cvt_tf32(As[buf][rb * GA_STRIDE + c + 4]);
                af[mt][3] = cvt_tf32(As[buf][(rb + 8) * GA_STRIDE + c + 4]);
            }
            unsigned bf[4][2];
            #pragma unroll
            for (int nt = 0; nt < 4; nt++) {
                int cb = warp_n * 32 + nt * 8 + gid;
                bf[nt][0] = cvt_tf32(Bs[buf][(ks * 8 + tig) * GB_STRIDE + cb]);
                bf[nt][1] = cvt_tf32(Bs[buf][(ks * 8 + tig + 4) * GB_STRIDE + cb]);
            }
            #pragma unroll
            for (int mt = 0; mt < 4; mt++)
                #pragma unroll
                for (int nt = 0; nt < 4; nt++) {
                    asm volatile(
                        "mma.sync.aligned.m16n8k8.row.col.f32.tf32.tf32.f32 "
                        "{%0,%1,%2,%3}, {%4,%5,%6,%7}, {%8,%9}, {%0,%1,%2,%3};"
                        : "+f"(acc[mt][nt][0]), "+f"(acc[mt][nt][1]),
                          "+f"(acc[mt][nt][2]), "+f"(acc[mt][nt][3])
                        : "r"(af[mt][0]), "r"(af[mt][1]), "r"(af[mt][2]), "r"(af[mt][3]),
                          "r"(bf[nt][0]), "r"(bf[nt][1]));
                }
        }
        __syncthreads();
    }

    #pragma unroll
    for (int mt = 0; mt < 4; mt++) {
        int r0 = rowBase + warp_m * 64 + mt * 16 + gid;
        int r1 = r0 + 8;
        #pragma unroll
        for (int nt = 0; nt < 4; nt++) {
            int col = colBase + warp_n * 32 + nt * 8 + 2 * tig;
            float b0 = 0.f, b1 = 0.f;
            if (use_bias) { b0 = bias[col]; b1 = bias[col + 1]; }
            if (r0 < M) {
                float2 v = make_float2(acc[mt][nt][0] + b0, acc[mt][nt][1] + b1);
                *(float2*)&C[(long)r0 * NC + col] = v;
            }
            if (r1 < M) {
                float2 v = make_float2(acc[mt][nt][2] + b0, acc[mt][nt][3] + b1);
                *(float2*)&C[(long)r1 * NC + col] = v;
            }
        }
    }
}

// ---------------- per-node attention scores: warp per (n,h) ----------------
__global__ void scores_kernel(const float* __restrict__ a_src,
                              const float* __restrict__ a_trg) {
    int w = (blockIdx.x * blockDim.x + threadIdx.x) >> 5;
    int lane = threadIdx.x & 31;
    if (w >= NN * HH) return;
    int n = w >> 2, h = w & 3;
    const float* p = (const float*)g_proj + n * 256 + h * 64;
    float p0 = p[lane], p1 = p[lane + 32];
    float vs = p0 * a_src[h * 64 + lane] + p1 * a_src[h * 64 + lane + 32];
    float vt = p0 * a_trg[h * 64 + lane] + p1 * a_trg[h * 64 + lane + 32];
    #pragma unroll
    for (int o = 16; o; o >>= 1) {
        vs += __shfl_xor_sync(0xffffffffu, vs, o);
        vt += __shfl_xor_sync(0xffffffffu, vt, o);
    }
    if (lane == 0) {
        ((float*)g_ssrc)[w] = vs;
        ((float*)g_strg)[w] = vt;
    }
}

// ---------------- fused edge pass: g_e = exp(leaky(ssrc[s]+strg[t])) ----------------
// (softmax is shift-invariant; global-max subtraction dropped — scores are O(±6))
__global__ void edgeAB_kernel(const int* __restrict__ esrc, const int* __restrict__ etrg) {
    int e = blockIdx.x * blockDim.x + threadIdx.x;
    if (e >= EE) return;
    int s = esrc[e], t = etrg[e];
    float4 ss = g_ssrc[s];
    float4 st = g_strg[t];
    float4 v;
    v.x = expf(leaky(ss.x + st.x));
    v.y = expf(leaky(ss.y + st.y));
    v.z = expf(leaky(ss.z + st.z));
    v.w = expf(leaky(ss.w + st.w));
    g_e[e] = v;
}

// ---------------- counting sort: histogram ----------------
__global__ void hist_kernel(const int* __restrict__ etrg) {
    int e = blockIdx.x * blockDim.x + threadIdx.x;
    if (e < EE) atomicAdd(&g_cnt[etrg[e]], 1);
}

// ---------------- scan step 1: per-block exclusive scan + block sums ----------------
__global__ void scan1_kernel() {
    __shared__ int s[256];
    int tid = threadIdx.x;
    int gi = blockIdx.x * 256 + tid;
    int v = (gi < NN) ? g_cnt[gi] : 0;
    s[tid] = v;
    __syncthreads();
    #pragma unroll
    for (int o = 1; o < 256; o <<= 1) {
        int t = (tid >= o) ? s[tid - o] : 0;
        __syncthreads();
        s[tid] += t;
        __syncthreads();
    }
    if (gi < NN) g_off[gi] = s[tid] - v;       // exclusive within block
    if (tid == 255) g_bsum[blockIdx.x] = s[255];
}

// ---------------- scan step 2: scan block sums (single block) ----------------
__global__ void scan2_kernel() {
    __shared__ int s[256];
    int tid = threadIdx.x;
    int v = (tid < NB) ? g_bsum[tid] : 0;
    s[tid] = v;
    __syncthreads();
    #pragma unroll
    for (int o = 1; o < 256; o <<= 1) {
        int t = (tid >= o) ? s[tid - o] : 0;
        __syncthreads();
        s[tid] += t;
        __syncthreads();
    }
    if (tid < NB) g_boff[tid] = s[tid] - v;    // exclusive
}

// ---------------- scan step 3: add block offsets ----------------
__global__ void scan3_kernel() {
    int gi = blockIdx.x * blockDim.x + threadIdx.x;
    if (gi < NN) g_off[gi] += g_boff[gi >> 8];
}

// ---------------- scatter edges into target-sorted order ----------------
__global__ void scatter_kernel(const int* __restrict__ etrg) {
    int e = blockIdx.x * blockDim.x + threadIdx.x;
    if (e >= EE) return;
    int t = etrg[e];
    int idx = g_off[t] + atomicAdd(&g_fill[t], 1);
    g_sorted[idx] = e;
}

// ---------------- aggregation: warp per target, no atomics, fused leaky ----------------
__global__ __launch_bounds__(256) void aggregate_kernel(const int* __restrict__ esrc,
                                                        float* __restrict__ out) {
    int w = (blockIdx.x * blockDim.x + threadIdx.x) >> 5;
    if (w >= NN) return;
    int lane = threadIdx.x & 31;
    int base = g_off[w];
    int deg  = g_fill[w];

    // pass 1: softmax denominator for this target (lane-parallel over edges)
    float4 dsum = make_float4(0.f, 0.f, 0.f, 0.f);
    for (int i = lane; i < deg; i += 32) {
        float4 v = g_e[g_sorted[base + i]];
        dsum.x += v.x; dsum.y += v.y; dsum.z += v.z; dsum.w += v.w;
    }
    #pragma unroll
    for (int o = 16; o; o >>= 1) {
        dsum.x += __shfl_xor_sync(0xffffffffu, dsum.x, o);
        dsum.y += __shfl_xor_sync(0xffffffffu, dsum.y, o);
        dsum.z += __shfl_xor_sync(0xffffffffu, dsum.z, o);
        dsum.w += __shfl_xor_sync(0xffffffffu, dsum.w, o);
    }
    float inv0 = 1.f / (dsum.x + 1e-16f);
    float inv1 = 1.f / (dsum.y + 1e-16f);
    float inv2 = 1.f / (dsum.z + 1e-16f);
    float inv3 = 1.f / (dsum.w + 1e-16f);

    // pass 2: weighted aggregation. Lane covers cols [4*lane,4*lane+4) and +128.
    float4 acc0 = make_float4(0.f, 0.f, 0.f, 0.f);
    float4 acc1 = make_float4(0.f, 0.f, 0.f, 0.f);
    bool hi = (lane >> 4);   // head parity within each 128-col half
    #pragma unroll 2
    for (int i = 0; i < deg; i++) {
        int e = g_sorted[base + i];   // uniform across warp -> broadcast
        int s = esrc[e];
        float4 ex = g_e[e];
        float a0 = (hi ? ex.y : ex.x) * (hi ? inv1 : inv0);
        float a1 = (hi ? ex.w : ex.z) * (hi ? inv3 : inv2);
        const float4* prow = &g_proj[s * 64];
        float4 p0 = prow[lane];
        float4 p1 = prow[lane + 32];
        acc0.x += p0.x * a0; acc0.y += p0.y * a0; acc0.z += p0.z * a0; acc0.w += p0.w * a0;
        acc1.x += p1.x * a1; acc1.y += p1.y * a1; acc1.z += p1.z * a1; acc1.w += p1.w * a1;
    }

    // read skip-projection (already in out), add, apply output leaky, store
    float* orow = out + (long)w * 256;
    float4 v0 = *(float4*)&orow[lane * 4];
    float4 v1 = *(float4*)&orow[128 + lane * 4];
    v0.x = leaky(v0.x + acc0.x); v0.y = leaky(v0.y + acc0.y);
    v0.z = leaky(v0.z + acc0.z); v0.w = leaky(v0.w + acc0.w);
    v1.x = leaky(v1.x + acc1.x); v1.y = leaky(v1.y + acc1.y);
    v1.z = leaky(v1.z + acc1.z); v1.w = leaky(v1.w + acc1.w);
    *(float4*)&orow[lane * 4]       = v0;
    *(float4*)&orow[128 + lane * 4] = v1;
}

// ---------------- launch ----------------
extern "C" void kernel_launch(void* const* d_in, const int* in_sizes, int n_in,
                              void* d_out, int out_size) {
    const float* x      = (const float*)d_in[0];
    const float* W      = (const float*)d_in[1];
    const float* a_src  = (const float*)d_in[2];
    const float* a_trg  = (const float*)d_in[3];
    const float* skip_w = (const float*)d_in[4];
    const float* bias   = (const float*)d_in[5];
    const int*   esrc   = (const int*)d_in[6];
    const int*   etrg   = (const int*)d_in[7];
    float* out = (float*)d_out;

    float* proj;
    cudaGetSymbolAddress((void**)&proj, g_proj);

    // 1. zero counters
    init_kernel<<<(NN + 255) / 256, 256>>>();

    // 2. both GEMMs (tf32 tensor cores): z=0 -> proj = x@W, z=1 -> out = x@skip_w + bias
    dim3 ggrid((NN + 127) / 128, 2, 2);
    gemm_tf32<<<ggrid, 256>>>(x, W, skip_w, proj, out, bias, NN);

    // 3. per-node attention scores
    scores_kernel<<<(NN * HH * 32 + 255) / 256, 256>>>(a_src, a_trg);

    // 4. edge exp-scores (no atomics, no global max)
    edgeAB_kernel<<<(EE + 255) / 256, 256>>>(esrc, etrg);

    // 5. counting sort of edges by target
    hist_kernel<<<(EE + 255) / 256, 256>>>(etrg);
    scan1_kernel<<<NB, 256>>>();
    scan2_kernel<<<1, 256>>>();
    scan3_kernel<<<NB, 256>>>();
    scatter_kernel<<<(EE + 255) / 256, 256>>>(etrg);

    // 6. warp-per-target aggregation (denom + weighted sum + skip + leaky), atomic-free
    aggregate_kernel<<<(NN * 32 + 255) / 256, 256>>>(esrc, out);
}

// round 6
// speedup vs baseline: 2.6636x; 1.1875x over previous
#include <cuda_runtime.h>
#include <cuda_fp16.h>
#include <math.h>
#include <stdint.h>

// Problem constants (GAT_19301583028500)
#define NN   50000      // nodes
#define EE   800000     // edges
#define IN_F 256        // in features (== H*F)
#define HH   4          // heads
#define FF   64         // per-head out features
#define SLOPE 0.2f
#define NB   ((NN + 255) / 256)   // scan blocks = 196

// ---------------- device scratch (no allocations allowed) ----------------
__device__ __half g_projh[NN * IN_F];       // [N,256] projected features, fp16 (25.6 MB)
__device__ float4 g_es   [EE];              // [E,4] exp(leaky(score)) in TARGET-SORTED order
__device__ int    g_srcs [EE];              // src node per sorted edge
__device__ float4 g_ssrc [NN];              // [N,4] source scores (atomically accumulated)
__device__ float4 g_strg [NN];              // [N,4] target scores
__device__ int    g_cnt  [NN];              // per-target degree histogram
__device__ int    g_off  [NN];              // exclusive-scan offsets
__device__ int    g_fill [NN];              // scatter fill counters
__device__ int    g_bsum [256];             // scan block sums
__device__ int    g_boff [256];             // scanned block sums

__device__ __forceinline__ float leaky(float v) { return v > 0.f ? v : SLOPE * v; }

__device__ __forceinline__ unsigned cvt_tf32(float f) {
    unsigned r;
    asm("cvt.rna.tf32.f32 %0, %1;" : "=r"(r) : "f"(f));
    return r;
}
__device__ __forceinline__ void cp_async16(unsigned smem_addr, const void* gptr) {
    asm volatile("cp.async.cg.shared.global [%0], [%1], 16;"
                 :: "r"(smem_addr), "l"(gptr) : "memory");
}
__device__ __forceinline__ void cp_commit() { asm volatile("cp.async.commit_group;" ::: "memory"); }
template<int N_> __device__ __forceinline__ void cp_wait() {
    asm volatile("cp.async.wait_group %0;" :: "n"(N_) : "memory");
}
__device__ __forceinline__ float sel4(float4 v, int h) {
    float lo = (h & 1) ? v.y : v.x;
    float hi = (h & 1) ? v.w : v.z;
    return (h & 2) ? hi : lo;
}

// ---------------- init: zero counters + score accumulators ----------------
__global__ void init_kernel() {
    int i = blockIdx.x * blockDim.x + threadIdx.x;
    if (i < NN) {
        g_cnt[i] = 0;
        g_fill[i] = 0;
        g_ssrc[i] = make_float4(0.f, 0.f, 0.f, 0.f);
        g_strg[i] = make_float4(0.f, 0.f, 0.f, 0.f);
    }
}

// ---------------- tf32 tensor-core GEMM with fused epilogues ----------------
// z=0: projh = half(x@W)  [N,256] + fused per-head score dots -> g_ssrc/g_strg
// z=1: out   = x@skip_w + bias (fp32)
#define GA_STRIDE 20
#define GB_STRIDE 136

__global__ __launch_bounds__(256) void gemm_tf32(const float* __restrict__ A,
                                                 const float* __restrict__ B0,
                                                 const float* __restrict__ B1,
                                                 float* __restrict__ out,
                                                 const float* __restrict__ bias,
                                                 const float* __restrict__ a_src,
                                                 const float* __restrict__ a_trg,
                                                 int M) {
    __shared__ float As[2][128 * GA_STRIDE];
    __shared__ float Bs[2][16  * GB_STRIDE];

    const int bz = blockIdx.z;
    const float* B = (bz == 0) ? B0 : B1;

    const int K = 256, NC = 256;
    const int tid  = threadIdx.x;
    const int wid  = tid >> 5;
    const int lane = tid & 31;
    const int gid  = lane >> 2;
    const int tig  = lane & 3;
    const int warp_m = wid & 1;
    const int warp_n = wid >> 1;

    const int rowBase = blockIdx.x * 128;
    const int colBase = blockIdx.y * 128;

    float acc[4][4][4];
    #pragma unroll
    for (int i = 0; i < 4; i++)
        #pragma unroll
        for (int j = 0; j < 4; j++)
            #pragma unroll
            for (int q = 0; q < 4; q++) acc[i][j][q] = 0.f;

    int aq0 = tid, aq1 = tid + 256;
    int ar0 = aq0 >> 2, as0 = aq0 & 3;
    int ar1 = aq1 >> 2, as1 = aq1 & 3;
    int grow0 = min(rowBase + ar0, M - 1);
    int grow1 = min(rowBase + ar1, M - 1);
    int bq0 = tid, bq1 = tid + 256;
    int br0 = bq0 >> 5, bs0 = bq0 & 31;
    int br1 = bq1 >> 5, bs1 = bq1 & 31;

    unsigned sA[2], sB[2];
    sA[0] = (unsigned)__cvta_generic_to_shared(&As[0][0]);
    sA[1] = (unsigned)__cvta_generic_to_shared(&As[1][0]);
    sB[0] = (unsigned)__cvta_generic_to_shared(&Bs[0][0]);
    sB[1] = (unsigned)__cvta_generic_to_shared(&Bs[1][0]);

    auto prefetch = [&](int kt, int buf) {
        const float* ga0 = &A[(long)grow0 * K + kt * 16 + as0 * 4];
        const float* ga1 = &A[(long)grow1 * K + kt * 16 + as1 * 4];
        cp_async16(sA[buf] + (ar0 * GA_STRIDE + as0 * 4) * 4, ga0);
        cp_async16(sA[buf] + (ar1 * GA_STRIDE + as1 * 4) * 4, ga1);
        const float* gb0 = &B[(kt * 16 + br0) * NC + colBase + bs0 * 4];
        const float* gb1 = &B[(kt * 16 + br1) * NC + colBase + bs1 * 4];
        cp_async16(sB[buf] + (br0 * GB_STRIDE + bs0 * 4) * 4, gb0);
        cp_async16(sB[buf] + (br1 * GB_STRIDE + bs1 * 4) * 4, gb1);
    };

    prefetch(0, 0);
    cp_commit();

    const int KT = K / 16;
    for (int kt = 0; kt < KT; kt++) {
        int buf = kt & 1;
        if (kt + 1 < KT) {
            prefetch(kt + 1, buf ^ 1);
            cp_commit();
            cp_wait<1>();
        } else {
            cp_wait<0>();
        }
        __syncthreads();

        #pragma unroll
        for (int ks = 0; ks < 2; ks++) {
            unsigned af[4][4];
            #pragma unroll
            for (int mt = 0; mt < 4; mt++) {
                int rb = warp_m * 64 + mt * 16 + gid;
                int c  = ks * 8 + tig;
                af[mt][0] = cvt_tf32(As[buf][rb * GA_STRIDE + c]);
                af[mt][1] = cvt_tf32(As[buf][(rb + 8) * GA_STRIDE + c]);
                af[mt][2] = cvt_tf32(As[buf][rb * GA_STRIDE + c + 4]);
                af[mt][3] = cvt_tf32(As[buf][(rb + 8) * GA_STRIDE + c + 4]);
            }
            unsigned bf[4][2];
            #pragma unroll
            for (int nt = 0; nt < 4; nt++) {
                int cb = warp_n * 32 + nt * 8 + gid;
                bf[nt][0] = cvt_tf32(Bs[buf][(ks * 8 + tig) * GB_STRIDE + cb]);
                bf[nt][1] = cvt_tf32(Bs[buf][(ks * 8 + tig + 4) * GB_STRIDE + cb]);
            }
            #pragma unroll
            for (int mt = 0; mt < 4; mt++)
                #pragma unroll
                for (int nt = 0; nt < 4; nt++) {
                    asm volatile(
                        "mma.sync.aligned.m16n8k8.row.col.f32.tf32.tf32.f32 "
                        "{%0,%1,%2,%3}, {%4,%5,%6,%7}, {%8,%9}, {%0,%1,%2,%3};"
                        : "+f"(acc[mt][nt][0]), "+f"(acc[mt][nt][1]),
                          "+f"(acc[mt][nt][2]), "+f"(acc[mt][nt][3])
                        : "r"(af[mt][0]), "r"(af[mt][1]), "r"(af[mt][2]), "r"(af[mt][3]),
                          "r"(bf[nt][0]), "r"(bf[nt][1]));
                }
        }
        __syncthreads();
    }

    if (bz == 0) {
        // ---- epilogue A: fused score partial dots -> red.add ----
        const int head = blockIdx.y * 2 + (warp_n >> 1);     // this warp's single head
        const float* Ah = a_src + head * 64;
        const float* Th = a_trg + head * 64;
        float avs[4][2], avt[4][2];
        #pragma unroll
        for (int nt = 0; nt < 4; nt++) {
            int f = (warp_n & 1) * 32 + nt * 8 + 2 * tig;    // col within head
            avs[nt][0] = Ah[f]; avs[nt][1] = Ah[f + 1];
            avt[nt][0] = Th[f]; avt[nt][1] = Th[f + 1];
        }
        float* S = (float*)g_ssrc;
        float* T = (float*)g_strg;
        #pragma unroll
        for (int mt = 0; mt < 4; mt++) {
            float s0 = 0.f, s1 = 0.f, t0 = 0.f, t1 = 0.f;
            #pragma unroll
            for (int nt = 0; nt < 4; nt++) {
                s0 += acc[mt][nt][0] * avs[nt][0] + acc[mt][nt][1] * avs[nt][1];
                s1 += acc[mt][nt][2] * avs[nt][0] + acc[mt][nt][3] * avs[nt][1];
                t0 += acc[mt][nt][0] * avt[nt][0] + acc[mt][nt][1] * avt[nt][1];
                t1 += acc[mt][nt][2] * avt[nt][0] + acc[mt][nt][3] * avt[nt][1];
            }
            #pragma unroll
            for (int o = 1; o < 4; o <<= 1) {
                s0 += __shfl_xor_sync(0xffffffffu, s0, o);
                s1 += __shfl_xor_sync(0xffffffffu, s1, o);
                t0 += __shfl_xor_sync(0xffffffffu, t0, o);
                t1 += __shfl_xor_sync(0xffffffffu, t1, o);
            }
            if (tig == 0) {
                int r0 = rowBase + warp_m * 64 + mt * 16 + gid;
                int r1 = r0 + 8;
                if (r0 < M) { atomicAdd(&S[r0 * 4 + head], s0); atomicAdd(&T[r0 * 4 + head], t0); }
                if (r1 < M) { atomicAdd(&S[r1 * 4 + head], s1); atomicAdd(&T[r1 * 4 + head], t1); }
            }
        }
        // ---- epilogue B: store fp16 proj ----
        #pragma unroll
        for (int mt = 0; mt < 4; mt++) {
            int r0 = rowBase + warp_m * 64 + mt * 16 + gid;
            int r1 = r0 + 8;
            #pragma unroll
            for (int nt = 0; nt < 4; nt++) {
                int col = colBase + warp_n * 32 + nt * 8 + 2 * tig;
                if (r0 < M)
                    *(__half2*)&g_projh[(long)r0 * NC + col] =
                        __floats2half2_rn(acc[mt][nt][0], acc[mt][nt][1]);
                if (r1 < M)
                    *(__half2*)&g_projh[(long)r1 * NC + col] =
                        __floats2half2_rn(acc[mt][nt][2], acc[mt][nt][3]);
            }
        }
    } else {
        // ---- epilogue: fp32 out = skip projection + bias ----
        #pragma unroll
        for (int mt = 0; mt < 4; mt++) {
            int r0 = rowBase + warp_m * 64 + mt * 16 + gid;
            int r1 = r0 + 8;
            #pragma unroll
            for (int nt = 0; nt < 4; nt++) {
                int col = colBase + warp_n * 32 + nt * 8 + 2 * tig;
                float b0 = bias[col], b1 = bias[col + 1];
                if (r0 < M) {
                    float2 v = make_float2(acc[mt][nt][0] + b0, acc[mt][nt][1] + b1);
                    *(float2*)&out[(long)r0 * NC + col] = v;
                }
                if (r1 < M) {
                    float2 v = make_float2(acc[mt][nt][2] + b0, acc[mt][nt][3] + b1);
                    *(float2*)&out[(long)r1 * NC + col] = v;
                }
            }
        }
    }
}

// ---------------- counting sort: histogram ----------------
__global__ void hist_kernel(const int* __restrict__ etrg) {
    int e = blockIdx.x * blockDim.x + threadIdx.x;
    if (e < EE) atomicAdd(&g_cnt[etrg[e]], 1);
}

// ---------------- scan step 1: per-block exclusive scan + block sums ----------------
__global__ void scan1_kernel() {
    __shared__ int s[256];
    int tid = threadIdx.x;
    int gi = blockIdx.x * 256 + tid;
    int v = (gi < NN) ? g_cnt[gi] : 0;
    s[tid] = v;
    __syncthreads();
    #pragma unroll
    for (int o = 1; o < 256; o <<= 1) {
        int t = (tid >= o) ? s[tid - o] : 0;
        __syncthreads();
        s[tid] += t;
        __syncthreads();
    }
    if (gi < NN) g_off[gi] = s[tid] - v;
    if (tid == 255) g_bsum[blockIdx.x] = s[255];
}

// ---------------- scan step 2: scan block sums (single block) ----------------
__global__ void scan2_kernel() {
    __shared__ int s[256];
    int tid = threadIdx.x;
    int v = (tid < NB) ? g_bsum[tid] : 0;
    s[tid] = v;
    __syncthreads();
    #pragma unroll
    for (int o = 1; o < 256; o <<= 1) {
        int t = (tid >= o) ? s[tid - o] : 0;
        __syncthreads();
        s[tid] += t;
        __syncthreads();
    }
    if (tid < NB) g_boff[tid] = s[tid] - v;
}

// ---------------- scan step 3: add block offsets ----------------
__global__ void scan3_kernel() {
    int gi = blockIdx.x * blockDim.x + threadIdx.x;
    if (gi < NN) g_off[gi] += g_boff[gi >> 8];
}

// ---------------- fused scatter: compute exp(leaky(score)), write sorted ----------------
__global__ void scatter_kernel(const int* __restrict__ esrc, const int* __restrict__ etrg) {
    int e = blockIdx.x * blockDim.x + threadIdx.x;
    if (e >= EE) return;
    int s = esrc[e], t = etrg[e];
    float4 ss = g_ssrc[s];
    float4 st = g_strg[t];
    float4 v;
    v.x = expf(leaky(ss.x + st.x));
    v.y = expf(leaky(ss.y + st.y));
    v.z = expf(leaky(ss.z + st.z));
    v.w = expf(leaky(ss.w + st.w));
    int idx = g_off[t] + atomicAdd(&g_fill[t], 1);
    g_es[idx] = v;
    g_srcs[idx] = s;
}

// ---------------- aggregation: warp per target, contiguous streams, fp16 gather ----------------
__global__ __launch_bounds__(256) void aggregate_kernel(float* __restrict__ out) {
    int w = (blockIdx.x * blockDim.x + threadIdx.x) >> 5;
    if (w >= NN) return;
    int lane = threadIdx.x & 31;
    int base = g_off[w];
    int deg  = g_cnt[w];

    // pass 1: softmax denominators (contiguous float4 stream)
    float4 dsum = make_float4(0.f, 0.f, 0.f, 0.f);
    for (int i = lane; i < deg; i += 32) {
        float4 v = g_es[base + i];
        dsum.x += v.x; dsum.y += v.y; dsum.z += v.z; dsum.w += v.w;
    }
    #pragma unroll
    for (int o = 16; o; o >>= 1) {
        dsum.x += __shfl_xor_sync(0xffffffffu, dsum.x, o);
        dsum.y += __shfl_xor_sync(0xffffffffu, dsum.y, o);
        dsum.z += __shfl_xor_sync(0xffffffffu, dsum.z, o);
        dsum.w += __shfl_xor_sync(0xffffffffu, dsum.w, o);
    }
    const int head = lane >> 3;                 // 8 cols per lane -> one head
    float invh = 1.f / (sel4(dsum, head) + 1e-16f);

    // pass 2: weighted aggregation; lane covers cols [8*lane, 8*lane+8)
    float2 acc0 = make_float2(0.f, 0.f), acc1 = acc0, acc2 = acc0, acc3 = acc0;
    const __half* ph = g_projh + (long)lane * 8;
    #pragma unroll 2
    for (int i = 0; i < deg; i++) {
        float4 ex = g_es[base + i];             // uniform -> broadcast
        int s = g_srcs[base + i];
        float a = sel4(ex, head) * invh;
        uint4 h = *(const uint4*)(ph + (long)s * 256);
        float2 f0 = __half22float2(*(__half2*)&h.x);
        float2 f1 = __half22float2(*(__half2*)&h.y);
        float2 f2 = __half22float2(*(__half2*)&h.z);
        float2 f3 = __half22float2(*(__half2*)&h.w);
        acc0.x += f0.x * a; acc0.y += f0.y * a;
        acc1.x += f1.x * a; acc1.y += f1.y * a;
        acc2.x += f2.x * a; acc2.y += f2.y * a;
        acc3.x += f3.x * a; acc3.y += f3.y * a;
    }

    // add skip projection (already in out), output leaky, store
    float* orow = out + (long)w * 256 + lane * 8;
    float4 v0 = *(float4*)orow;
    float4 v1 = *(float4*)(orow + 4);
    v0.x = leaky(v0.x + acc0.x); v0.y = leaky(v0.y + acc0.y);
    v0.z = leaky(v0.z + acc1.x); v0.w = leaky(v0.w + acc1.y);
    v1.x = leaky(v1.x + acc2.x); v1.y = leaky(v1.y + acc2.y);
    v1.z = leaky(v1.z + acc3.x); v1.w = leaky(v1.w + acc3.y);
    *(float4*)orow       = v0;
    *(float4*)(orow + 4) = v1;
}

// ---------------- launch ----------------
extern "C" void kernel_launch(void* const* d_in, const int* in_sizes, int n_in,
                              void* d_out, int out_size) {
    const float* x      = (const float*)d_in[0];
    const float* W      = (const float*)d_in[1];
    const float* a_src  = (const float*)d_in[2];
    const float* a_trg  = (const float*)d_in[3];
    const float* skip_w = (const float*)d_in[4];
    const float* bias   = (const float*)d_in[5];
    const int*   esrc   = (const int*)d_in[6];
    const int*   etrg   = (const int*)d_in[7];
    float* out = (float*)d_out;

    // 1. zero counters + score accumulators
    init_kernel<<<(NN + 255) / 256, 256>>>();

    // 2. counting-sort prep (independent of GEMM)
    hist_kernel<<<(EE + 255) / 256, 256>>>(etrg);
    scan1_kernel<<<NB, 256>>>();
    scan2_kernel<<<1, 256>>>();
    scan3_kernel<<<NB, 256>>>();

    // 3. both GEMMs (tf32): z=0 -> projh(half) + fused scores, z=1 -> out = x@skip_w + bias
    dim3 ggrid((NN + 127) / 128, 2, 2);
    gemm_tf32<<<ggrid, 256>>>(x, W, skip_w, out, bias, a_src, a_trg, NN);

    // 4. fused edge-score + scatter into target-sorted order
    scatter_kernel<<<(EE + 255) / 256, 256>>>(esrc, etrg);

    // 5. warp-per-target aggregation (denom + weighted sum + skip + leaky), atomic-free
    aggregate_kernel<<<(NN * 32 + 255) / 256, 256>>>(out);
}

// round 7
// speedup vs baseline: 3.1203x; 1.1715x over previous
#include <cuda_runtime.h>
#include <cuda_fp16.h>
#include <math.h>
#include <stdint.h>

// Problem constants (GAT_19301583028500)
#define NN   50000      // nodes
#define EE   800000     // edges
#define IN_F 256        // in features (== H*F)
#define HH   4          // heads
#define FF   64         // per-head out features
#define SLOPE 0.2f
#define NB   ((NN + 255) / 256)   // scan blocks = 196

// ---------------- device scratch (no allocations allowed) ----------------
__device__ __half g_projh[NN * IN_F];       // [N,256] projected features, fp16 (25.6 MB)
__device__ __half g_xh   [NN * IN_F];       // x in fp16 (12.8 MB)
__device__ __half g_wt   [2 * IN_F * IN_F]; // W^T and skip^T, half, [n][k] layout
__device__ float4 g_es   [EE];              // [E,4] exp(leaky(score)) in TARGET-SORTED order
__device__ int    g_srcs [EE];              // src node per sorted edge
__device__ float4 g_ssrc [NN];              // [N,4] source scores (atomically accumulated)
__device__ float4 g_strg [NN];              // [N,4] target scores
__device__ int    g_cnt  [NN];              // per-target degree histogram
__device__ int    g_off  [NN];              // exclusive-scan offsets
__device__ int    g_fill [NN];              // scatter fill counters
__device__ int    g_bsum [256];             // scan block sums

__device__ __forceinline__ float leaky(float v) { return v > 0.f ? v : SLOPE * v; }

__device__ __forceinline__ void cp_async16(unsigned smem_addr, const void* gptr) {
    asm volatile("cp.async.cg.shared.global [%0], [%1], 16;"
                 :: "r"(smem_addr), "l"(gptr) : "memory");
}
__device__ __forceinline__ void cp_commit() { asm volatile("cp.async.commit_group;" ::: "memory"); }
template<int N_> __device__ __forceinline__ void cp_wait() {
    asm volatile("cp.async.wait_group %0;" :: "n"(N_) : "memory");
}
__device__ __forceinline__ float sel4(float4 v, int h) {
    float lo = (h & 1) ? v.y : v.x;
    float hi = (h & 1) ? v.w : v.z;
    return (h & 2) ? hi : lo;
}

// ---------------- init: zero counters + score accumulators ----------------
__global__ void init_kernel() {
    int i = blockIdx.x * blockDim.x + threadIdx.x;
    if (i < NN) {
        g_cnt[i] = 0;
        g_fill[i] = 0;
        g_ssrc[i] = make_float4(0.f, 0.f, 0.f, 0.f);
        g_strg[i] = make_float4(0.f, 0.f, 0.f, 0.f);
    }
}

// ---------------- convert x -> fp16 ----------------
__global__ void convert_x_kernel(const float* __restrict__ x) {
    int i = blockIdx.x * blockDim.x + threadIdx.x;    // 8 floats per thread
    if (i >= NN * (IN_F / 8)) return;
    const float4* xp = (const float4*)x + (long)i * 2;
    float4 v0 = xp[0], v1 = xp[1];
    __half2 h0 = __floats2half2_rn(v0.x, v0.y);
    __half2 h1 = __floats2half2_rn(v0.z, v0.w);
    __half2 h2 = __floats2half2_rn(v1.x, v1.y);
    __half2 h3 = __floats2half2_rn(v1.z, v1.w);
    uint4 o;
    o.x = *(unsigned*)&h0; o.y = *(unsigned*)&h1;
    o.z = *(unsigned*)&h2; o.w = *(unsigned*)&h3;
    *(uint4*)&g_xh[(long)i * 8] = o;
}

// ---------------- convert W, skip_w -> transposed fp16 [n][k] ----------------
__global__ void convert_w_kernel(const float* __restrict__ W, const float* __restrict__ S) {
    int i = blockIdx.x * blockDim.x + threadIdx.x;    // (m, k, n), n fastest
    if (i >= 2 * IN_F * IN_F) return;
    int m = i >> 16;
    int rem = i & 65535;
    int k = rem >> 8, n = rem & 255;
    const float* src = m ? S : W;
    g_wt[m * 65536 + n * 256 + k] = __float2half(src[k * 256 + n]);   // coalesced read
}

// ---------------- fp16 tensor-core GEMM (mma.m16n8k16) with fused epilogues ----------------
// z=0: projh = half(xh@W)  + fused per-head score dots -> g_ssrc/g_strg
// z=1: out   = xh@skip_w + bias (fp32)
// CTA 128x128, BK=32, 8 warps (warp tile 64x32). Smem stride 40 halves (conflict-free).
#define HS 40

__global__ __launch_bounds__(256) void gemm_fp16(float* __restrict__ out,
                                                 const float* __restrict__ bias,
                                                 const float* __restrict__ a_src,
                                                 const float* __restrict__ a_trg,
                                                 int M) {
    __shared__ __half As [2][128 * HS];
    __shared__ __half BsT[2][128 * HS];

    const int bz = blockIdx.z;
    const __half* Ah = g_xh;
    const __half* Bt = g_wt + bz * 65536;

    const int NC = 256;
    const int tid  = threadIdx.x;
    const int wid  = tid >> 5;
    const int lane = tid & 31;
    const int gid  = lane >> 2;
    const int tig  = lane & 3;
    const int warp_m = wid & 1;
    const int warp_n = wid >> 1;

    const int rowBase = blockIdx.x * 128;
    const int colBase = blockIdx.y * 128;

    float acc[4][4][4];
    #pragma unroll
    for (int i = 0; i < 4; i++)
        #pragma unroll
        for (int j = 0; j < 4; j++)
            #pragma unroll
            for (int q = 0; q < 4; q++) acc[i][j][q] = 0.f;

    unsigned sA[2], sB[2];
    sA[0] = (unsigned)__cvta_generic_to_shared(&As[0][0]);
    sA[1] = (unsigned)__cvta_generic_to_shared(&As[1][0]);
    sB[0] = (unsigned)__cvta_generic_to_shared(&BsT[0][0]);
    sB[1] = (unsigned)__cvta_generic_to_shared(&BsT[1][0]);

    // tile = 128 rows x 32 halves = 512 16B chunks; 2 per thread (A and B each)
    auto prefetch = [&](int kt, int buf) {
        #pragma unroll
        for (int it = 0; it < 2; it++) {
            int c = tid + it * 256;
            int r = c >> 2, seg = c & 3;
            int grow = min(rowBase + r, M - 1);
            cp_async16(sA[buf] + (r * HS + seg * 8) * 2,
                       &Ah[(long)grow * 256 + kt * 32 + seg * 8]);
            cp_async16(sB[buf] + (r * HS + seg * 8) * 2,
                       &Bt[(long)(colBase + r) * 256 + kt * 32 + seg * 8]);
        }
    };

    prefetch(0, 0);
    cp_commit();

    const int KT = 8;    // 256/32
    for (int kt = 0; kt < KT; kt++) {
        int buf = kt & 1;
        if (kt + 1 < KT) {
            prefetch(kt + 1, buf ^ 1);
            cp_commit();
            cp_wait<1>();
        } else {
            cp_wait<0>();
        }
        __syncthreads();

        #pragma unroll
        for (int ks = 0; ks < 2; ks++) {
            unsigned af[4][4];
            #pragma unroll
            for (int mt = 0; mt < 4; mt++) {
                int rb = (warp_m * 64 + mt * 16 + gid) * HS + ks * 16 + 2 * tig;
                af[mt][0] = *(unsigned*)&As[buf][rb];
                af[mt][1] = *(unsigned*)&As[buf][rb + 8 * HS];
                af[mt][2] = *(unsigned*)&As[buf][rb + 8];
                af[mt][3] = *(unsigned*)&As[buf][rb + 8 * HS + 8];
            }
            unsigned bf[4][2];
            #pragma unroll
            for (int nt = 0; nt < 4; nt++) {
                int cb = (warp_n * 32 + nt * 8 + gid) * HS + ks * 16 + 2 * tig;
                bf[nt][0] = *(unsigned*)&BsT[buf][cb];
                bf[nt][1] = *(unsigned*)&BsT[buf][cb + 8];
            }
            #pragma unroll
            for (int mt = 0; mt < 4; mt++)
                #pragma unroll
                for (int nt = 0; nt < 4; nt++) {
                    asm volatile(
                        "mma.sync.aligned.m16n8k16.row.col.f32.f16.f16.f32 "
                        "{%0,%1,%2,%3}, {%4,%5,%6,%7}, {%8,%9}, {%0,%1,%2,%3};"
                        : "+f"(acc[mt][nt][0]), "+f"(acc[mt][nt][1]),
                          "+f"(acc[mt][nt][2]), "+f"(acc[mt][nt][3])
                        : "r"(af[mt][0]), "r"(af[mt][1]), "r"(af[mt][2]), "r"(af[mt][3]),
                          "r"(bf[nt][0]), "r"(bf[nt][1]));
                }
        }
        __syncthreads();
    }

    if (bz == 0) {
        // ---- epilogue A: fused score partial dots -> atomic add ----
        const int head = blockIdx.y * 2 + (warp_n >> 1);
        const float* Ahd = a_src + head * 64;
        const float* Thd = a_trg + head * 64;
        float avs[4][2], avt[4][2];
        #pragma unroll
        for (int nt = 0; nt < 4; nt++) {
            int f = (warp_n & 1) * 32 + nt * 8 + 2 * tig;
            avs[nt][0] = Ahd[f]; avs[nt][1] = Ahd[f + 1];
            avt[nt][0] = Thd[f]; avt[nt][1] = Thd[f + 1];
        }
        float* S = (float*)g_ssrc;
        float* T = (float*)g_strg;
        #pragma unroll
        for (int mt = 0; mt < 4; mt++) {
            float s0 = 0.f, s1 = 0.f, t0 = 0.f, t1 = 0.f;
            #pragma unroll
            for (int nt = 0; nt < 4; nt++) {
                s0 += acc[mt][nt][0] * avs[nt][0] + acc[mt][nt][1] * avs[nt][1];
                s1 += acc[mt][nt][2] * avs[nt][0] + acc[mt][nt][3] * avs[nt][1];
                t0 += acc[mt][nt][0] * avt[nt][0] + acc[mt][nt][1] * avt[nt][1];
                t1 += acc[mt][nt][2] * avt[nt][0] + acc[mt][nt][3] * avt[nt][1];
            }
            #pragma unroll
            for (int o = 1; o < 4; o <<= 1) {
                s0 += __shfl_xor_sync(0xffffffffu, s0, o);
                s1 += __shfl_xor_sync(0xffffffffu, s1, o);
                t0 += __shfl_xor_sync(0xffffffffu, t0, o);
                t1 += __shfl_xor_sync(0xffffffffu, t1, o);
            }
            if (tig == 0) {
                int r0 = rowBase + warp_m * 64 + mt * 16 + gid;
                int r1 = r0 + 8;
                if (r0 < M) { atomicAdd(&S[r0 * 4 + head], s0); atomicAdd(&T[r0 * 4 + head], t0); }
                if (r1 < M) { atomicAdd(&S[r1 * 4 + head], s1); atomicAdd(&T[r1 * 4 + head], t1); }
            }
        }
        // ---- epilogue B: store fp16 proj ----
        #pragma unroll
        for (int mt = 0; mt < 4; mt++) {
            int r0 = rowBase + warp_m * 64 + mt * 16 + gid;
            int r1 = r0 + 8;
            #pragma unroll
            for (int nt = 0; nt < 4; nt++) {
                int col = colBase + warp_n * 32 + nt * 8 + 2 * tig;
                if (r0 < M)
                    *(__half2*)&g_projh[(long)r0 * NC + col] =
                        __floats2half2_rn(acc[mt][nt][0], acc[mt][nt][1]);
                if (r1 < M)
                    *(__half2*)&g_projh[(long)r1 * NC + col] =
                        __floats2half2_rn(acc[mt][nt][2], acc[mt][nt][3]);
            }
        }
    } else {
        // ---- epilogue: fp32 out = skip projection + bias ----
        #pragma unroll
        for (int mt = 0; mt < 4; mt++) {
            int r0 = rowBase + warp_m * 64 + mt * 16 + gid;
            int r1 = r0 + 8;
            #pragma unroll
            for (int nt = 0; nt < 4; nt++) {
                int col = colBase + warp_n * 32 + nt * 8 + 2 * tig;
                float b0 = bias[col], b1 = bias[col + 1];
                if (r0 < M) {
                    float2 v = make_float2(acc[mt][nt][0] + b0, acc[mt][nt][1] + b1);
                    *(float2*)&out[(long)r0 * NC + col] = v;
                }
                if (r1 < M) {
                    float2 v = make_float2(acc[mt][nt][2] + b0, acc[mt][nt][3] + b1);
                    *(float2*)&out[(long)r1 * NC + col] = v;
                }
            }
        }
    }
}

// ---------------- counting sort: histogram ----------------
__global__ void hist_kernel(const int* __restrict__ etrg) {
    int e = blockIdx.x * blockDim.x + threadIdx.x;
    if (e < EE) atomicAdd(&g_cnt[etrg[e]], 1);
}

// ---------------- scan step 1: per-block exclusive scan + block sums ----------------
__global__ void scan1_kernel() {
    __shared__ int s[256];
    int tid = threadIdx.x;
    int gi = blockIdx.x * 256 + tid;
    int v = (gi < NN) ? g_cnt[gi] : 0;
    s[tid] = v;
    __syncthreads();
    #pragma unroll
    for (int o = 1; o < 256; o <<= 1) {
        int t = (tid >= o) ? s[tid - o] : 0;
        __syncthreads();
        s[tid] += t;
        __syncthreads();
    }
    if (gi < NN) g_off[gi] = s[tid] - v;
    if (tid == 255) g_bsum[blockIdx.x] = s[255];
}

// ---------------- scan steps 2+3 fused: every block scans bsums, applies its prefix ----------------
__global__ void scan23_kernel() {
    __shared__ int s[256];
    int tid = threadIdx.x;
    int v = (tid < NB) ? g_bsum[tid] : 0;
    s[tid] = v;
    __syncthreads();
    #pragma unroll
    for (int o = 1; o < 256; o <<= 1) {
        int t = (tid >= o) ? s[tid - o] : 0;
        __syncthreads();
        s[tid] += t;
        __syncthreads();
    }
    int myoff = (blockIdx.x == 0) ? 0 : s[blockIdx.x - 1];
    int gi = blockIdx.x * 256 + tid;
    if (gi < NN) g_off[gi] += myoff;
}

// ---------------- fused scatter: compute exp(leaky(score)), write sorted ----------------
__global__ void scatter_kernel(const int* __restrict__ esrc, const int* __restrict__ etrg) {
    int e = blockIdx.x * blockDim.x + threadIdx.x;
    if (e >= EE) return;
    int s = esrc[e], t = etrg[e];
    float4 ss = g_ssrc[s];
    float4 st = g_strg[t];
    float4 v;
    v.x = expf(leaky(ss.x + st.x));
    v.y = expf(leaky(ss.y + st.y));
    v.z = expf(leaky(ss.z + st.z));
    v.w = expf(leaky(ss.w + st.w));
    int idx = g_off[t] + atomicAdd(&g_fill[t], 1);
    g_es[idx] = v;
    g_srcs[idx] = s;
}

// ---------------- aggregation: warp per target, contiguous streams, fp16 gather ----------------
__global__ __launch_bounds__(256) void aggregate_kernel(float* __restrict__ out) {
    int w = (blockIdx.x * blockDim.x + threadIdx.x) >> 5;
    if (w >= NN) return;
    int lane = threadIdx.x & 31;
    int base = g_off[w];
    int deg  = g_cnt[w];

    // pass 1: softmax denominators (contiguous float4 stream)
    float4 dsum = make_float4(0.f, 0.f, 0.f, 0.f);
    for (int i = lane; i < deg; i += 32) {
        float4 v = g_es[base + i];
        dsum.x += v.x; dsum.y += v.y; dsum.z += v.z; dsum.w += v.w;
    }
    #pragma unroll
    for (int o = 16; o; o >>= 1) {
        dsum.x += __shfl_xor_sync(0xffffffffu, dsum.x, o);
        dsum.y += __shfl_xor_sync(0xffffffffu, dsum.y, o);
        dsum.z += __shfl_xor_sync(0xffffffffu, dsum.z, o);
        dsum.w += __shfl_xor_sync(0xffffffffu, dsum.w, o);
    }
    const int head = lane >> 3;
    float invh = 1.f / (sel4(dsum, head) + 1e-16f);

    // pass 2: weighted aggregation; lane covers cols [8*lane, 8*lane+8)
    float2 acc0 = make_float2(0.f, 0.f), acc1 = acc0, acc2 = acc0, acc3 = acc0;
    const __half* ph = g_projh + (long)lane * 8;
    #pragma unroll 2
    for (int i = 0; i < deg; i++) {
        float4 ex = g_es[base + i];
        int s = g_srcs[base + i];
        float a = sel4(ex, head) * invh;
        uint4 h = *(const uint4*)(ph + (long)s * 256);
        float2 f0 = __half22float2(*(__half2*)&h.x);
        float2 f1 = __half22float2(*(__half2*)&h.y);
        float2 f2 = __half22float2(*(__half2*)&h.z);
        float2 f3 = __half22float2(*(__half2*)&h.w);
        acc0.x += f0.x * a; acc0.y += f0.y * a;
        acc1.x += f1.x * a; acc1.y += f1.y * a;
        acc2.x += f2.x * a; acc2.y += f2.y * a;
        acc3.x += f3.x * a; acc3.y += f3.y * a;
    }

    float* orow = out + (long)w * 256 + lane * 8;
    float4 v0 = *(float4*)orow;
    float4 v1 = *(float4*)(orow + 4);
    v0.x = leaky(v0.x + acc0.x); v0.y = leaky(v0.y + acc0.y);
    v0.z = leaky(v0.z + acc1.x); v0.w = leaky(v0.w + acc1.y);
    v1.x = leaky(v1.x + acc2.x); v1.y = leaky(v1.y + acc2.y);
    v1.z = leaky(v1.z + acc3.x); v1.w = leaky(v1.w + acc3.y);
    *(float4*)orow       = v0;
    *(float4*)(orow + 4) = v1;
}

// ---------------- launch ----------------
extern "C" void kernel_launch(void* const* d_in, const int* in_sizes, int n_in,
                              void* d_out, int out_size) {
    const float* x      = (const float*)d_in[0];
    const float* W      = (const float*)d_in[1];
    const float* a_src  = (const float*)d_in[2];
    const float* a_trg  = (const float*)d_in[3];
    const float* skip_w = (const float*)d_in[4];
    const float* bias   = (const float*)d_in[5];
    const int*   esrc   = (const int*)d_in[6];
    const int*   etrg   = (const int*)d_in[7];
    float* out = (float*)d_out;

    // 1. zero counters + score accumulators
    init_kernel<<<(NN + 255) / 256, 256>>>();

    // 2. fp16 conversions
    convert_x_kernel<<<(NN * 32 + 255) / 256, 256>>>(x);
    convert_w_kernel<<<(2 * IN_F * IN_F + 255) / 256, 256>>>(W, skip_w);

    // 3. counting-sort prep
    hist_kernel<<<(EE + 255) / 256, 256>>>(etrg);
    scan1_kernel<<<NB, 256>>>();
    scan23_kernel<<<NB, 256>>>();

    // 4. both GEMMs (fp16 mma): z=0 -> projh + fused scores, z=1 -> out = x@skip_w + bias
    dim3 ggrid((NN + 127) / 128, 2, 2);
    gemm_fp16<<<ggrid, 256>>>(out, bias, a_src, a_trg, NN);

    // 5. fused edge-score + scatter into target-sorted order
    scatter_kernel<<<(EE + 255) / 256, 256>>>(esrc, etrg);

    // 6. warp-per-target aggregation (denom + weighted sum + skip + leaky), atomic-free
    aggregate_kernel<<<(NN * 32 + 255) / 256, 256>>>(out);
}

// round 8
// speedup vs baseline: 3.2547x; 1.0430x over previous
#include <cuda_runtime.h>
#include <cuda_fp16.h>
#include <math.h>
#include <stdint.h>

// Problem constants (GAT_19301583028500)
#define NN   50000      // nodes
#define EE   800000     // edges
#define IN_F 256        // in features (== H*F)
#define HH   4          // heads
#define FF   64         // per-head out features
#define SLOPE 0.2f
#define NB   ((NN + 255) / 256)   // scan blocks = 196

// ---------------- device scratch (no allocations allowed) ----------------
__device__ __half g_projh[NN * IN_F];       // [N,256] projected features, fp16 (25.6 MB)
__device__ __half g_xh   [NN * IN_F];       // x in fp16 (12.8 MB)
__device__ __half g_wt   [2 * IN_F * IN_F]; // W^T and skip^T, half, [n][k] layout
__device__ float4 g_es   [EE];              // [E,4] exp(leaky(score)) in TARGET-SORTED order
__device__ int    g_srcs [EE];              // src node per sorted edge
__device__ float4 g_ssrc [NN];              // [N,4] source scores (atomically accumulated)
__device__ float4 g_strg [NN];              // [N,4] target scores
__device__ int    g_cnt  [NN];              // per-target degree histogram
__device__ int    g_off  [NN];              // exclusive-scan offsets
__device__ int    g_fill [NN];              // scatter fill counters
__device__ int    g_bsum [256];             // scan block sums

__device__ __forceinline__ float leaky(float v) { return v > 0.f ? v : SLOPE * v; }

__device__ __forceinline__ void cp_async16(unsigned smem_addr, const void* gptr) {
    asm volatile("cp.async.cg.shared.global [%0], [%1], 16;"
                 :: "r"(smem_addr), "l"(gptr) : "memory");
}
__device__ __forceinline__ void cp_commit() { asm volatile("cp.async.commit_group;" ::: "memory"); }
template<int N_> __device__ __forceinline__ void cp_wait() {
    asm volatile("cp.async.wait_group %0;" :: "n"(N_) : "memory");
}
__device__ __forceinline__ float sel4(float4 v, int h) {
    float lo = (h & 1) ? v.y : v.x;
    float hi = (h & 1) ? v.w : v.z;
    return (h & 2) ? hi : lo;
}

// ---------------- sort-side init: zero histogram + fill counters ----------------
__global__ void init_sort_kernel() {
    int i = blockIdx.x * blockDim.x + threadIdx.x;
    if (i < NN) { g_cnt[i] = 0; g_fill[i] = 0; }
}

// ---------------- convert x -> fp16 (+ fold score-accumulator zeroing) ----------------
__global__ void convert_x_kernel(const float* __restrict__ x) {
    int i = blockIdx.x * blockDim.x + threadIdx.x;    // 8 floats per thread
    if (i < NN) {
        g_ssrc[i] = make_float4(0.f, 0.f, 0.f, 0.f);
        g_strg[i] = make_float4(0.f, 0.f, 0.f, 0.f);
    }
    if (i >= NN * (IN_F / 8)) return;
    const float4* xp = (const float4*)x + (long)i * 2;
    float4 v0 = xp[0], v1 = xp[1];
    __half2 h0 = __floats2half2_rn(v0.x, v0.y);
    __half2 h1 = __floats2half2_rn(v0.z, v0.w);
    __half2 h2 = __floats2half2_rn(v1.x, v1.y);
    __half2 h3 = __floats2half2_rn(v1.z, v1.w);
    uint4 o;
    o.x = *(unsigned*)&h0; o.y = *(unsigned*)&h1;
    o.z = *(unsigned*)&h2; o.w = *(unsigned*)&h3;
    *(uint4*)&g_xh[(long)i * 8] = o;
}

// ---------------- convert W, skip_w -> transposed fp16 [n][k] ----------------
__global__ void convert_w_kernel(const float* __restrict__ W, const float* __restrict__ S) {
    int i = blockIdx.x * blockDim.x + threadIdx.x;    // (m, k, n), n fastest
    if (i >= 2 * IN_F * IN_F) return;
    int m = i >> 16;
    int rem = i & 65535;
    int k = rem >> 8, n = rem & 255;
    const float* src = m ? S : W;
    g_wt[m * 65536 + n * 256 + k] = __float2half(src[k * 256 + n]);   // coalesced read
}

// ---------------- fp16 tensor-core GEMM (mma.m16n8k16) with fused epilogues ----------------
// zsel=0: projh = half(xh@W)  + fused per-head score dots -> g_ssrc/g_strg
// zsel=1: out   = xh@skip_w + bias (fp32)
// CTA 128x128, BK=32, 8 warps (warp tile 64x32). Smem stride 40 halves (conflict-free).
#define HS 40

__global__ __launch_bounds__(256) void gemm_fp16(float* __restrict__ out,
                                                 const float* __restrict__ bias,
                                                 const float* __restrict__ a_src,
                                                 const float* __restrict__ a_trg,
                                                 int M, int zsel) {
    __shared__ __half As [2][128 * HS];
    __shared__ __half BsT[2][128 * HS];

    const __half* Ah = g_xh;
    const __half* Bt = g_wt + zsel * 65536;

    const int NC = 256;
    const int tid  = threadIdx.x;
    const int wid  = tid >> 5;
    const int lane = tid & 31;
    const int gid  = lane >> 2;
    const int tig  = lane & 3;
    const int warp_m = wid & 1;
    const int warp_n = wid >> 1;

    const int rowBase = blockIdx.x * 128;
    const int colBase = blockIdx.y * 128;

    float acc[4][4][4];
    #pragma unroll
    for (int i = 0; i < 4; i++)
        #pragma unroll
        for (int j = 0; j < 4; j++)
            #pragma unroll
            for (int q = 0; q < 4; q++) acc[i][j][q] = 0.f;

    unsigned sA[2], sB[2];
    sA[0] = (unsigned)__cvta_generic_to_shared(&As[0][0]);
    sA[1] = (unsigned)__cvta_generic_to_shared(&As[1][0]);
    sB[0] = (unsigned)__cvta_generic_to_shared(&BsT[0][0]);
    sB[1] = (unsigned)__cvta_generic_to_shared(&BsT[1][0]);

    auto prefetch = [&](int kt, int buf) {
        #pragma unroll
        for (int it = 0; it < 2; it++) {
            int c = tid + it * 256;
            int r = c >> 2, seg = c & 3;
            int grow = min(rowBase + r, M - 1);
            cp_async16(sA[buf] + (r * HS + seg * 8) * 2,
                       &Ah[(long)grow * 256 + kt * 32 + seg * 8]);
            cp_async16(sB[buf] + (r * HS + seg * 8) * 2,
                       &Bt[(long)(colBase + r) * 256 + kt * 32 + seg * 8]);
        }
    };

    prefetch(0, 0);
    cp_commit();

    const int KT = 8;    // 256/32
    for (int kt = 0; kt < KT; kt++) {
        int buf = kt & 1;
        if (kt + 1 < KT) {
            prefetch(kt + 1, buf ^ 1);
            cp_commit();
            cp_wait<1>();
        } else {
            cp_wait<0>();
        }
        __syncthreads();

        #pragma unroll
        for (int ks = 0; ks < 2; ks++) {
            unsigned af[4][4];
            #pragma unroll
            for (int mt = 0; mt < 4; mt++) {
                int rb = (warp_m * 64 + mt * 16 + gid) * HS + ks * 16 + 2 * tig;
                af[mt][0] = *(unsigned*)&As[buf][rb];
                af[mt][1] = *(unsigned*)&As[buf][rb + 8 * HS];
                af[mt][2] = *(unsigned*)&As[buf][rb + 8];
                af[mt][3] = *(unsigned*)&As[buf][rb + 8 * HS + 8];
            }
            unsigned bf[4][2];
            #pragma unroll
            for (int nt = 0; nt < 4; nt++) {
                int cb = (warp_n * 32 + nt * 8 + gid) * HS + ks * 16 + 2 * tig;
                bf[nt][0] = *(unsigned*)&BsT[buf][cb];
                bf[nt][1] = *(unsigned*)&BsT[buf][cb + 8];
            }
            #pragma unroll
            for (int mt = 0; mt < 4; mt++)
                #pragma unroll
                for (int nt = 0; nt < 4; nt++) {
                    asm volatile(
                        "mma.sync.aligned.m16n8k16.row.col.f32.f16.f16.f32 "
                        "{%0,%1,%2,%3}, {%4,%5,%6,%7}, {%8,%9}, {%0,%1,%2,%3};"
                        : "+f"(acc[mt][nt][0]), "+f"(acc[mt][nt][1]),
                          "+f"(acc[mt][nt][2]), "+f"(acc[mt][nt][3])
                        : "r"(af[mt][0]), "r"(af[mt][1]), "r"(af[mt][2]), "r"(af[mt][3]),
                          "r"(bf[nt][0]), "r"(bf[nt][1]));
                }
        }
        __syncthreads();
    }

    if (zsel == 0) {
        // ---- epilogue A: fused score partial dots -> atomic add ----
        const int head = blockIdx.y * 2 + (warp_n >> 1);
        const float* Ahd = a_src + head * 64;
        const float* Thd = a_trg + head * 64;
        float avs[4][2], avt[4][2];
        #pragma unroll
        for (int nt = 0; nt < 4; nt++) {
            int f = (warp_n & 1) * 32 + nt * 8 + 2 * tig;
            avs[nt][0] = Ahd[f]; avs[nt][1] = Ahd[f + 1];
            avt[nt][0] = Thd[f]; avt[nt][1] = Thd[f + 1];
        }
        float* S = (float*)g_ssrc;
        float* T = (float*)g_strg;
        #pragma unroll
        for (int mt = 0; mt < 4; mt++) {
            float s0 = 0.f, s1 = 0.f, t0 = 0.f, t1 = 0.f;
            #pragma unroll
            for (int nt = 0; nt < 4; nt++) {
                s0 += acc[mt][nt][0] * avs[nt][0] + acc[mt][nt][1] * avs[nt][1];
                s1 += acc[mt][nt][2] * avs[nt][0] + acc[mt][nt][3] * avs[nt][1];
                t0 += acc[mt][nt][0] * avt[nt][0] + acc[mt][nt][1] * avt[nt][1];
                t1 += acc[mt][nt][2] * avt[nt][0] + acc[mt][nt][3] * avt[nt][1];
            }
            #pragma unroll
            for (int o = 1; o < 4; o <<= 1) {
                s0 += __shfl_xor_sync(0xffffffffu, s0, o);
                s1 += __shfl_xor_sync(0xffffffffu, s1, o);
                t0 += __shfl_xor_sync(0xffffffffu, t0, o);
                t1 += __shfl_xor_sync(0xffffffffu, t1, o);
            }
            if (tig == 0) {
                int r0 = rowBase + warp_m * 64 + mt * 16 + gid;
                int r1 = r0 + 8;
                if (r0 < M) { atomicAdd(&S[r0 * 4 + head], s0); atomicAdd(&T[r0 * 4 + head], t0); }
                if (r1 < M) { atomicAdd(&S[r1 * 4 + head], s1); atomicAdd(&T[r1 * 4 + head], t1); }
            }
        }
        // ---- epilogue B: store fp16 proj ----
        #pragma unroll
        for (int mt = 0; mt < 4; mt++) {
            int r0 = rowBase + warp_m * 64 + mt * 16 + gid;
            int r1 = r0 + 8;
            #pragma unroll
            for (int nt = 0; nt < 4; nt++) {
                int col = colBase + warp_n * 32 + nt * 8 + 2 * tig;
                if (r0 < M)
                    *(__half2*)&g_projh[(long)r0 * NC + col] =
                        __floats2half2_rn(acc[mt][nt][0], acc[mt][nt][1]);
                if (r1 < M)
                    *(__half2*)&g_projh[(long)r1 * NC + col] =
                        __floats2half2_rn(acc[mt][nt][2], acc[mt][nt][3]);
            }
        }
    } else {
        // ---- epilogue: fp32 out = skip projection + bias ----
        #pragma unroll
        for (int mt = 0; mt < 4; mt++) {
            int r0 = rowBase + warp_m * 64 + mt * 16 + gid;
            int r1 = r0 + 8;
            #pragma unroll
            for (int nt = 0; nt < 4; nt++) {
                int col = colBase + warp_n * 32 + nt * 8 + 2 * tig;
                float b0 = bias[col], b1 = bias[col + 1];
                if (r0 < M) {
                    float2 v = make_float2(acc[mt][nt][0] + b0, acc[mt][nt][1] + b1);
                    *(float2*)&out[(long)r0 * NC + col] = v;
                }
                if (r1 < M) {
                    float2 v = make_float2(acc[mt][nt][2] + b0, acc[mt][nt][3] + b1);
                    *(float2*)&out[(long)r1 * NC + col] = v;
                }
            }
        }
    }
}

// ---------------- counting sort: histogram ----------------
__global__ void hist_kernel(const int* __restrict__ etrg) {
    int e = blockIdx.x * blockDim.x + threadIdx.x;
    if (e < EE) atomicAdd(&g_cnt[etrg[e]], 1);
}

// ---------------- scan step 1: per-block exclusive scan + block sums ----------------
__global__ void scan1_kernel() {
    __shared__ int s[256];
    int tid = threadIdx.x;
    int gi = blockIdx.x * 256 + tid;
    int v = (gi < NN) ? g_cnt[gi] : 0;
    s[tid] = v;
    __syncthreads();
    #pragma unroll
    for (int o = 1; o < 256; o <<= 1) {
        int t = (tid >= o) ? s[tid - o] : 0;
        __syncthreads();
        s[tid] += t;
        __syncthreads();
    }
    if (gi < NN) g_off[gi] = s[tid] - v;
    if (tid == 255) g_bsum[blockIdx.x] = s[255];
}

// ---------------- scan steps 2+3 fused ----------------
__global__ void scan23_kernel() {
    __shared__ int s[256];
    int tid = threadIdx.x;
    int v = (tid < NB) ? g_bsum[tid] : 0;
    s[tid] = v;
    __syncthreads();
    #pragma unroll
    for (int o = 1; o < 256; o <<= 1) {
        int t = (tid >= o) ? s[tid - o] : 0;
        __syncthreads();
        s[tid] += t;
        __syncthreads();
    }
    int myoff = (blockIdx.x == 0) ? 0 : s[blockIdx.x - 1];
    int gi = blockIdx.x * 256 + tid;
    if (gi < NN) g_off[gi] += myoff;
}

// ---------------- fused scatter: compute exp(leaky(score)), write sorted ----------------
__global__ void scatter_kernel(const int* __restrict__ esrc, const int* __restrict__ etrg) {
    int e = blockIdx.x * blockDim.x + threadIdx.x;
    if (e >= EE) return;
    int s = esrc[e], t = etrg[e];
    float4 ss = g_ssrc[s];
    float4 st = g_strg[t];
    float4 v;
    v.x = expf(leaky(ss.x + st.x));
    v.y = expf(leaky(ss.y + st.y));
    v.z = expf(leaky(ss.z + st.z));
    v.w = expf(leaky(ss.w + st.w));
    int idx = g_off[t] + atomicAdd(&g_fill[t], 1);
    g_es[idx] = v;
    g_srcs[idx] = s;
}

// ---------------- aggregation: warp per target, contiguous streams, fp16 gather ----------------
__global__ __launch_bounds__(256) void aggregate_kernel(float* __restrict__ out) {
    int w = (blockIdx.x * blockDim.x + threadIdx.x) >> 5;
    if (w >= NN) return;
    int lane = threadIdx.x & 31;
    int base = g_off[w];
    int deg  = g_cnt[w];

    // pass 1: softmax denominators (contiguous float4 stream)
    float4 dsum = make_float4(0.f, 0.f, 0.f, 0.f);
    for (int i = lane; i < deg; i += 32) {
        float4 v = g_es[base + i];
        dsum.x += v.x; dsum.y += v.y; dsum.z += v.z; dsum.w += v.w;
    }
    #pragma unroll
    for (int o = 16; o; o >>= 1) {
        dsum.x += __shfl_xor_sync(0xffffffffu, dsum.x, o);
        dsum.y += __shfl_xor_sync(0xffffffffu, dsum.y, o);
        dsum.z += __shfl_xor_sync(0xffffffffu, dsum.z, o);
        dsum.w += __shfl_xor_sync(0xffffffffu, dsum.w, o);
    }
    const int head = lane >> 3;
    float invh = 1.f / (sel4(dsum, head) + 1e-16f);

    // pass 2: weighted aggregation; lane covers cols [8*lane, 8*lane+8)
    float2 acc0 = make_float2(0.f, 0.f), acc1 = acc0, acc2 = acc0, acc3 = acc0;
    const __half* ph = g_projh + (long)lane * 8;
    #pragma unroll 2
    for (int i = 0; i < deg; i++) {
        float4 ex = g_es[base + i];
        int s = g_srcs[base + i];
        float a = sel4(ex, head) * invh;
        uint4 h = *(const uint4*)(ph + (long)s * 256);
        float2 f0 = __half22float2(*(__half2*)&h.x);
        float2 f1 = __half22float2(*(__half2*)&h.y);
        float2 f2 = __half22float2(*(__half2*)&h.z);
        float2 f3 = __half22float2(*(__half2*)&h.w);
        acc0.x += f0.x * a; acc0.y += f0.y * a;
        acc1.x += f1.x * a; acc1.y += f1.y * a;
        acc2.x += f2.x * a; acc2.y += f2.y * a;
        acc3.x += f3.x * a; acc3.y += f3.y * a;
    }

    float* orow = out + (long)w * 256 + lane * 8;
    float4 v0 = *(float4*)orow;
    float4 v1 = *(float4*)(orow + 4);
    v0.x = leaky(v0.x + acc0.x); v0.y = leaky(v0.y + acc0.y);
    v0.z = leaky(v0.z + acc1.x); v0.w = leaky(v0.w + acc1.y);
    v1.x = leaky(v1.x + acc2.x); v1.y = leaky(v1.y + acc2.y);
    v1.z = leaky(v1.z + acc3.x); v1.w = leaky(v1.w + acc3.y);
    *(float4*)orow       = v0;
    *(float4*)(orow + 4) = v1;
}

// ---------------- launch: fork-join stream DAG (graph-capturable) ----------------
extern "C" void kernel_launch(void* const* d_in, const int* in_sizes, int n_in,
                              void* d_out, int out_size) {
    const float* x      = (const float*)d_in[0];
    const float* W      = (const float*)d_in[1];
    const float* a_src  = (const float*)d_in[2];
    const float* a_trg  = (const float*)d_in[3];
    const float* skip_w = (const float*)d_in[4];
    const float* bias   = (const float*)d_in[5];
    const int*   esrc   = (const int*)d_in[6];
    const int*   etrg   = (const int*)d_in[7];
    float* out = (float*)d_out;

    // one-time infra (created on the uncaptured correctness call; reused under capture)
    static cudaStream_t sSort = nullptr, sScat = nullptr;
    static cudaEvent_t evFork = nullptr, evSort = nullptr, evZ0 = nullptr, evScat = nullptr;
    if (!sSort) {
        cudaStreamCreateWithFlags(&sSort, cudaStreamNonBlocking);
        cudaStreamCreateWithFlags(&sScat, cudaStreamNonBlocking);
        cudaEventCreateWithFlags(&evFork, cudaEventDisableTiming);
        cudaEventCreateWithFlags(&evSort, cudaEventDisableTiming);
        cudaEventCreateWithFlags(&evZ0,   cudaEventDisableTiming);
        cudaEventCreateWithFlags(&evScat, cudaEventDisableTiming);
    }

    // ---- fork: sort chain on sSort, concurrent with converts+GEMMs ----
    cudaEventRecord(evFork, 0);
    cudaStreamWaitEvent(sSort, evFork, 0);
    init_sort_kernel<<<(NN + 255) / 256, 256, 0, sSort>>>();
    hist_kernel<<<(EE + 255) / 256, 256, 0, sSort>>>(etrg);
    scan1_kernel<<<NB, 256, 0, sSort>>>();
    scan23_kernel<<<NB, 256, 0, sSort>>>();
    cudaEventRecord(evSort, sSort);

    // ---- main: converts, then proj GEMM (z=0, fused scores) ----
    convert_x_kernel<<<(NN * 32 + 255) / 256, 256>>>(x);
    convert_w_kernel<<<(2 * IN_F * IN_F + 255) / 256, 256>>>(W, skip_w);
    dim3 ggrid((NN + 127) / 128, 2);
    gemm_fp16<<<ggrid, 256>>>(out, bias, a_src, a_trg, NN, 0);
    cudaEventRecord(evZ0, 0);

    // ---- scatter on sScat (needs scores + sort), concurrent with skip GEMM ----
    cudaStreamWaitEvent(sScat, evZ0, 0);
    cudaStreamWaitEvent(sScat, evSort, 0);
    scatter_kernel<<<(EE + 255) / 256, 256, 0, sScat>>>(esrc, etrg);
    cudaEventRecord(evScat, sScat);

    // ---- main: skip GEMM (z=1) concurrent with scatter ----
    gemm_fp16<<<ggrid, 256>>>(out, bias, a_src, a_trg, NN, 1);

    // ---- join, then aggregate ----
    cudaStreamWaitEvent(0, evScat, 0);
    aggregate_kernel<<<(NN * 32 + 255) / 256, 256>>>(out);
}